// round 1
// baseline (speedup 1.0000x reference)
#include <cuda_runtime.h>

// causal_attention: B=8, C=128, H=W=64 -> N=4096 tokens, d=128.
// Inputs (metadata order): key, mixin (=V), query; all [B, C, N] fp32
// (channel-major, token index contiguous). Output [B, C, N] fp32.
//
// Strategy: fp32 flash-attention, 1 CTA per (batch, 128-row Q tile),
// 256 threads, register tiles 8x4 (S) and 8x8 (O). Exact reference
// semantics: masked logits shifted by -1e10 (participate in row max),
// masked probs forced to 0, denominator gets +1e-6.

#define MASK_ALL 0xffffffffu

constexpr int NSEQ = 4096;
constexpr int CDIM = 128;

// SMEM layout (float offsets)
constexpr int QS_OFF    = 0;                       // Q [c][m], 128x128
constexpr int KS_OFF    = QS_OFF + 128 * 128;      // K [c][j], stride 64
constexpr int VS_STRIDE = 132;                     // padded (16B-aligned rows)
constexpr int VS_OFF    = KS_OFF + 128 * 64;       // V^T [j][c], 64 rows
constexpr int PS_STRIDE = 68;                      // padded
constexpr int PS_OFF    = VS_OFF + 64 * VS_STRIDE; // P [m][j], 128 rows
constexpr int SMEM_FLOATS = PS_OFF + 128 * PS_STRIDE;
constexpr int SMEM_BYTES  = SMEM_FLOATS * 4;       // 166,912 B

// 1/sqrt(128) * log2(e)
__device__ __forceinline__ float scl() { return 0.12751744955161f; }

__global__ __launch_bounds__(256, 1)
void attn_kernel(const float* __restrict__ key,
                 const float* __restrict__ mixin,
                 const float* __restrict__ query,
                 float* __restrict__ out)
{
    extern __shared__ float sm[];

    const int tid = threadIdx.x;
    const int tx  = tid & 15;   // 16 cols of threads
    const int ty  = tid >> 4;   // 16 rows of threads (owns m-rows ty*8..+7)

    // Big Q-tiles first for wave balance: qt descending.
    const int bx = blockIdx.x;
    const int qt = 31 - (bx >> 3);
    const int b  = bx & 7;
    const int m0 = qt * 128;

    const float* qptr = query + (size_t)b * CDIM * NSEQ + m0;
    const float* kptr = key   + (size_t)b * CDIM * NSEQ;
    const float* vptr = mixin + (size_t)b * CDIM * NSEQ;

    // ---- load Q tile into SMEM as [c][m] (gmem is token-contiguous -> free) ----
    for (int idx = tid; idx < 128 * 32; idx += 256) {
        const int c  = idx >> 5;
        const int mq = (idx & 31) << 2;
        float4 v = *(const float4*)(qptr + (size_t)c * NSEQ + mq);
        *(float4*)(sm + QS_OFF + c * 128 + mq) = v;
    }

    float o[8][8];
    float mrun[8], lrun[8];
#pragma unroll
    for (int mm = 0; mm < 8; ++mm) {
        mrun[mm] = -3.0e38f;
        lrun[mm] = 0.0f;
#pragma unroll
        for (int cc = 0; cc < 8; ++cc) o[mm][cc] = 0.0f;
    }

    const int nkt = qt * 2 + 2;  // k-tiles of 64 up to (and incl.) the diagonal band

    for (int kt = 0; kt < nkt; ++kt) {
        const int j0 = kt * 64;

        __syncthreads();  // previous PV done reading Ks/Vs/Ps

        // K tile: [c][j] direct copy
        for (int idx = tid; idx < 128 * 16; idx += 256) {
            const int c  = idx >> 4;
            const int jj = (idx & 15) << 2;
            float4 v = *(const float4*)(kptr + (size_t)c * NSEQ + j0 + jj);
            *(float4*)(sm + KS_OFF + c * 64 + jj) = v;
        }
        // V tile: transpose to [j][c]
        for (int idx = tid; idx < 128 * 16; idx += 256) {
            const int c  = idx >> 4;
            const int j4 = (idx & 15) << 2;
            float4 v = *(const float4*)(vptr + (size_t)c * NSEQ + j0 + j4);
            sm[VS_OFF + (j4 + 0) * VS_STRIDE + c] = v.x;
            sm[VS_OFF + (j4 + 1) * VS_STRIDE + c] = v.y;
            sm[VS_OFF + (j4 + 2) * VS_STRIDE + c] = v.z;
            sm[VS_OFF + (j4 + 3) * VS_STRIDE + c] = v.w;
        }
        __syncthreads();

        // ---- S = Q K^T  (reduction over c; 8m x 4j per thread) ----
        float s[8][4];
#pragma unroll
        for (int mm = 0; mm < 8; ++mm)
#pragma unroll
            for (int jj = 0; jj < 4; ++jj) s[mm][jj] = 0.0f;

        const float* qb = sm + QS_OFF + ty * 8;
        const float* kb = sm + KS_OFF + tx * 4;
#pragma unroll 2
        for (int c = 0; c < 128; ++c) {
            float qr[8], kr[4];
            *(float4*)(qr)     = *(const float4*)(qb + c * 128);
            *(float4*)(qr + 4) = *(const float4*)(qb + c * 128 + 4);
            *(float4*)(kr)     = *(const float4*)(kb + c * 64);
#pragma unroll
            for (int mm = 0; mm < 8; ++mm)
#pragma unroll
                for (int jj = 0; jj < 4; ++jj)
                    s[mm][jj] = fmaf(qr[mm], kr[jj], s[mm][jj]);
        }

        // ---- online softmax (exact reference semantics) ----
        const bool tmask = (j0 + 63 >= m0);  // only last two tiles touch the mask
#pragma unroll
        for (int mm = 0; mm < 8; ++mm) {
            const int ig = m0 + ty * 8 + mm;
            if (tmask) {
#pragma unroll
                for (int jj = 0; jj < 4; ++jj)
                    if (j0 + tx * 4 + jj >= ig) s[mm][jj] = -1.0e10f;
            }
            float rmax = fmaxf(fmaxf(s[mm][0], s[mm][1]), fmaxf(s[mm][2], s[mm][3]));
#pragma unroll
            for (int w = 1; w < 16; w <<= 1)
                rmax = fmaxf(rmax, __shfl_xor_sync(MASK_ALL, rmax, w, 32));

            const float mnew  = fmaxf(mrun[mm], rmax);
            const float alpha = exp2f((mrun[mm] - mnew) * scl());

            float ps = 0.0f;
#pragma unroll
            for (int jj = 0; jj < 4; ++jj) {
                float p;
                if (tmask && (j0 + tx * 4 + jj >= ig)) p = 0.0f;  // probs *= mask
                else p = exp2f((s[mm][jj] - mnew) * scl());
                s[mm][jj] = p;
                ps += p;
            }
#pragma unroll
            for (int w = 1; w < 16; w <<= 1)
                ps += __shfl_xor_sync(MASK_ALL, ps, w, 32);

            lrun[mm] = lrun[mm] * alpha + ps;
            mrun[mm] = mnew;
#pragma unroll
            for (int cc = 0; cc < 8; ++cc) o[mm][cc] *= alpha;
        }

        // ---- stage P to SMEM [m][j] ----
#pragma unroll
        for (int mm = 0; mm < 8; ++mm)
            *(float4*)(sm + PS_OFF + (ty * 8 + mm) * PS_STRIDE + tx * 4) =
                make_float4(s[mm][0], s[mm][1], s[mm][2], s[mm][3]);
        __syncthreads();

        // ---- O += P V  (reduction over j, 2 j per step; 8m x 8c per thread) ----
        const float* pb = sm + PS_OFF + (ty * 8) * PS_STRIDE;
        const float* vb = sm + VS_OFF + tx * 8;
        for (int j = 0; j < 64; j += 2) {
            float2 p2[8];
#pragma unroll
            for (int mm = 0; mm < 8; ++mm)
                p2[mm] = *(const float2*)(pb + mm * PS_STRIDE + j);
            float va[8], vc[8];
            *(float4*)(va)     = *(const float4*)(vb + (size_t)j * VS_STRIDE);
            *(float4*)(va + 4) = *(const float4*)(vb + (size_t)j * VS_STRIDE + 4);
            *(float4*)(vc)     = *(const float4*)(vb + (size_t)(j + 1) * VS_STRIDE);
            *(float4*)(vc + 4) = *(const float4*)(vb + (size_t)(j + 1) * VS_STRIDE + 4);
#pragma unroll
            for (int mm = 0; mm < 8; ++mm)
#pragma unroll
                for (int cc = 0; cc < 8; ++cc) {
                    o[mm][cc] = fmaf(p2[mm].x, va[cc], o[mm][cc]);
                    o[mm][cc] = fmaf(p2[mm].y, vc[cc], o[mm][cc]);
                }
        }
    }

    // ---- epilogue: divide by (l + 1e-6), stage transposed, coalesced store ----
    float inv[8];
#pragma unroll
    for (int mm = 0; mm < 8; ++mm) inv[mm] = 1.0f / (lrun[mm] + 1e-6f);

    __syncthreads();
#pragma unroll
    for (int mm = 0; mm < 8; ++mm)
#pragma unroll
        for (int cc = 0; cc < 8; ++cc)
            sm[QS_OFF + (tx * 8 + cc) * 128 + ty * 8 + mm] = o[mm][cc] * inv[mm];
    __syncthreads();

    float* optr = out + (size_t)b * CDIM * NSEQ + m0;
    for (int idx = tid; idx < 128 * 32; idx += 256) {
        const int c  = idx >> 5;
        const int mq = (idx & 31) << 2;
        *(float4*)(optr + (size_t)c * NSEQ + mq) =
            *(const float4*)(sm + QS_OFF + c * 128 + mq);
    }
}

extern "C" void kernel_launch(void* const* d_in, const int* in_sizes, int n_in,
                              void* d_out, int out_size)
{
    const float* key   = (const float*)d_in[0];
    const float* mixin = (const float*)d_in[1];
    const float* query = (const float*)d_in[2];
    float* out = (float*)d_out;

    cudaFuncSetAttribute(attn_kernel,
                         cudaFuncAttributeMaxDynamicSharedMemorySize, SMEM_BYTES);
    attn_kernel<<<256, 256, SMEM_BYTES>>>(key, mixin, query, out);
}

// round 4
// speedup vs baseline: 2.5663x; 2.5663x over previous
#include <cuda_runtime.h>
#include <cuda_bf16.h>
#include <cstdint>

// causal_attention: B=8, N=4096, d=128, fp32 [B,C,N] channel-major in/out.
// HMMA (mma.sync m16n8k16 bf16) flash attention, fp32 via bf16 hi/lo split
// (3 MMAs per GEMM). Plain-sm_103-compatible: no tcgen05/TMEM.

constexpr int NSEQ = 4096;
constexpr int CDIM = 128;

// SMEM: bf16 tiles, row stride 128 bf16 = 256B, 16B-granule XOR swizzle
// (granule' = granule ^ (row & 7)) -> conflict-free STS.128 fill + ldmatrix.
constexpr int SM_QHI = 0;          // 128 x 128 bf16 (32KB)
constexpr int SM_QLO = 32768;
constexpr int SM_KHI = 65536;      // 64 x 128 bf16 (16KB)
constexpr int SM_KLO = 81920;
constexpr int SM_VHI = 98304;
constexpr int SM_VLO = 114688;
constexpr int SMEM_BYTES = 131072;

// 1/sqrt(128) * log2(e)
#define SCL 0.12751744955161f

__device__ __forceinline__ uint32_t su32(const void* p) {
    uint32_t a;
    asm("{ .reg .u64 t; cvta.to.shared.u64 t, %1; cvt.u32.u64 %0, t; }" : "=r"(a) : "l"(p));
    return a;
}

// pack two f32 -> bf16x2 (lo = a, hi = b), round-to-nearest
__device__ __forceinline__ uint32_t pack_bf16(float a, float b) {
    uint32_t r;
    asm("cvt.rn.bf16x2.f32 %0, %1, %2;" : "=r"(r) : "f"(b), "f"(a));
    return r;
}
__device__ __forceinline__ float bf_lo(uint32_t u) { return __uint_as_float(u << 16); }
__device__ __forceinline__ float bf_hi(uint32_t u) { return __uint_as_float(u & 0xffff0000u); }

__device__ __forceinline__ void ldsm4(uint32_t addr, uint32_t& r0, uint32_t& r1,
                                      uint32_t& r2, uint32_t& r3) {
    asm volatile("ldmatrix.sync.aligned.m8n8.x4.shared.b16 {%0,%1,%2,%3}, [%4];"
                 : "=r"(r0), "=r"(r1), "=r"(r2), "=r"(r3) : "r"(addr));
}
__device__ __forceinline__ void ldsm4t(uint32_t addr, uint32_t& r0, uint32_t& r1,
                                       uint32_t& r2, uint32_t& r3) {
    asm volatile("ldmatrix.sync.aligned.m8n8.x4.trans.shared.b16 {%0,%1,%2,%3}, [%4];"
                 : "=r"(r0), "=r"(r1), "=r"(r2), "=r"(r3) : "r"(addr));
}

__device__ __forceinline__ void mma16816(float* d, uint32_t a0, uint32_t a1,
                                         uint32_t a2, uint32_t a3,
                                         uint32_t b0, uint32_t b1) {
    asm volatile(
        "mma.sync.aligned.m16n8k16.row.col.f32.bf16.bf16.f32 "
        "{%0,%1,%2,%3}, {%4,%5,%6,%7}, {%8,%9}, {%0,%1,%2,%3};"
        : "+f"(d[0]), "+f"(d[1]), "+f"(d[2]), "+f"(d[3])
        : "r"(a0), "r"(a1), "r"(a2), "r"(a3), "r"(b0), "r"(b1));
}

// per-lane ldmatrix.x4 address covering a 16-row x 16-col bf16 region.
// lanes 0-7: rows rb+0..7 @ col cb; 8-15: rows rb+8..15 @ cb;
// 16-23: rows rb+0..7 @ cb+8; 24-31: rows rb+8..15 @ cb+8.
__device__ __forceinline__ uint32_t frag_addr(uint32_t base, int rb, int cb, int l) {
    int row = rb + (l & 7) + ((l >> 3) & 1) * 8;
    int col = cb + ((l >> 4) << 3);
    return base + (row << 8) + ((((col >> 3) ^ (row & 7)) << 4));
}

// gmem fp32 [c][token] -> smem bf16 hi/lo [row][c], swizzled, R rows.
template <int R>
__device__ __forceinline__ void fill_tile(char* smem, int hi_off, int lo_off,
                                          const float* gsrc, int tok0, int tid) {
    constexpr int SH = (R == 128) ? 7 : 6;
    for (int it = tid; it < R * 16; it += 256) {
        const int r  = it & (R - 1);
        const int c8 = (it >> SH) << 3;
        const float* g = gsrc + (size_t)c8 * NSEQ + tok0 + r;
        uint32_t hi[4], lo[4];
#pragma unroll
        for (int p = 0; p < 4; ++p) {
            float a = g[(size_t)(2 * p) * NSEQ];
            float c = g[(size_t)(2 * p + 1) * NSEQ];
            uint32_t h = pack_bf16(a, c);
            hi[p] = h;
            lo[p] = pack_bf16(a - bf_lo(h), c - bf_hi(h));
        }
        const int off = (r << 8) + ((((c8 >> 3) ^ (r & 7)) << 4));
        *(uint4*)(smem + hi_off + off) = make_uint4(hi[0], hi[1], hi[2], hi[3]);
        *(uint4*)(smem + lo_off + off) = make_uint4(lo[0], lo[1], lo[2], lo[3]);
    }
}

__global__ __launch_bounds__(256, 1)
void attn_hmma_kernel(const float* __restrict__ key,
                      const float* __restrict__ mixin,
                      const float* __restrict__ query,
                      float* __restrict__ out)
{
    extern __shared__ char smem[];
    const uint32_t sb = su32(smem);

    const int tid = threadIdx.x;
    const int l   = tid & 31;
    const int w   = tid >> 5;

    // big q-tiles first for wave balance
    const int bx = blockIdx.x;
    const int qt = 31 - (bx >> 3);
    const int b  = bx & 7;
    const int m0 = qt * 128;

    const size_t bCN = (size_t)b * CDIM * NSEQ;

    // prologue: Q tile (rows = m)
    fill_tile<128>(smem, SM_QHI, SM_QLO, query + bCN, m0, tid);

    // per-thread softmax state: rows (w*16 + l/4) and (+8)
    const int qr  = l >> 2;
    const int qc  = (l & 3) << 1;
    const int ig0 = m0 + (w << 4) + qr;
    const int ig1 = ig0 + 8;

    float o[16][4];
#pragma unroll
    for (int g = 0; g < 16; ++g)
#pragma unroll
        for (int e = 0; e < 4; ++e) o[g][e] = 0.0f;
    float mr0 = -3.0e38f, mr1 = -3.0e38f, lr0 = 0.0f, lr1 = 0.0f;

    const int nkt = qt * 2 + 2;

    for (int kt = 0; kt < nkt; ++kt) {
        const int j0 = kt * 64;

        __syncthreads();  // previous iteration done reading K/V (and Q fill on iter 0)
        fill_tile<64>(smem, SM_KHI, SM_KLO, key + bCN, j0, tid);
        fill_tile<64>(smem, SM_VHI, SM_VLO, mixin + bCN, j0, tid);
        __syncthreads();

        // ---- S = Q K^T: s[8 groups][4], rows (qr, qr+8), cols 8g+qc+{0,1} ----
        float s[8][4];
#pragma unroll
        for (int g = 0; g < 8; ++g)
#pragma unroll
            for (int e = 0; e < 4; ++e) s[g][e] = 0.0f;

#pragma unroll
        for (int ck = 0; ck < 8; ++ck) {
            uint32_t ah0, ah1, ah2, ah3, al0, al1, al2, al3;
            ldsm4(frag_addr(sb + SM_QHI, w << 4, ck << 4, l), ah0, ah1, ah2, ah3);
            ldsm4(frag_addr(sb + SM_QLO, w << 4, ck << 4, l), al0, al1, al2, al3);
#pragma unroll
            for (int g2 = 0; g2 < 4; ++g2) {
                uint32_t kh0, kh1, kh2, kh3, kl0, kl1, kl2, kl3;
                ldsm4(frag_addr(sb + SM_KHI, g2 << 4, ck << 4, l), kh0, kh1, kh2, kh3);
                ldsm4(frag_addr(sb + SM_KLO, g2 << 4, ck << 4, l), kl0, kl1, kl2, kl3);
                mma16816(s[2 * g2],     ah0, ah1, ah2, ah3, kh0, kh2);
                mma16816(s[2 * g2],     ah0, ah1, ah2, ah3, kl0, kl2);
                mma16816(s[2 * g2],     al0, al1, al2, al3, kh0, kh2);
                mma16816(s[2 * g2 + 1], ah0, ah1, ah2, ah3, kh1, kh3);
                mma16816(s[2 * g2 + 1], ah0, ah1, ah2, ah3, kl1, kl3);
                mma16816(s[2 * g2 + 1], al0, al1, al2, al3, kh1, kh3);
            }
        }

        // ---- online softmax (warp-local; rows span lanes differing in bits 0-1) ----
        const bool tm = (j0 + 63 >= m0 + (w << 4));
        if (tm) {
#pragma unroll
            for (int g = 0; g < 8; ++g) {
                const int jg = j0 + (g << 3) + qc;
                if (jg     >= ig0) s[g][0] = -1.0e10f;
                if (jg + 1 >= ig0) s[g][1] = -1.0e10f;
                if (jg     >= ig1) s[g][2] = -1.0e10f;
                if (jg + 1 >= ig1) s[g][3] = -1.0e10f;
            }
        }
        float mx0 = -3.0e38f, mx1 = -3.0e38f;
#pragma unroll
        for (int g = 0; g < 8; ++g) {
            mx0 = fmaxf(mx0, fmaxf(s[g][0], s[g][1]));
            mx1 = fmaxf(mx1, fmaxf(s[g][2], s[g][3]));
        }
        mx0 = fmaxf(mx0, __shfl_xor_sync(0xffffffffu, mx0, 1, 32));
        mx0 = fmaxf(mx0, __shfl_xor_sync(0xffffffffu, mx0, 2, 32));
        mx1 = fmaxf(mx1, __shfl_xor_sync(0xffffffffu, mx1, 1, 32));
        mx1 = fmaxf(mx1, __shfl_xor_sync(0xffffffffu, mx1, 2, 32));

        const float mn0 = fmaxf(mr0, mx0), mn1 = fmaxf(mr1, mx1);
        const float a0  = exp2f((mr0 - mn0) * SCL);
        const float a1  = exp2f((mr1 - mn1) * SCL);

        float s0 = 0.0f, s1 = 0.0f;
#pragma unroll
        for (int g = 0; g < 8; ++g) {
#pragma unroll
            for (int e = 0; e < 2; ++e) {
                const int jg = j0 + (g << 3) + qc + e;
                float p0 = (tm && jg >= ig0) ? 0.0f : exp2f((s[g][e] - mn0) * SCL);
                float p1 = (tm && jg >= ig1) ? 0.0f : exp2f((s[g][2 + e] - mn1) * SCL);
                s[g][e] = p0; s[g][2 + e] = p1;
                s0 += p0; s1 += p1;
            }
        }
        s0 += __shfl_xor_sync(0xffffffffu, s0, 1, 32);
        s0 += __shfl_xor_sync(0xffffffffu, s0, 2, 32);
        s1 += __shfl_xor_sync(0xffffffffu, s1, 1, 32);
        s1 += __shfl_xor_sync(0xffffffffu, s1, 2, 32);

        lr0 = lr0 * a0 + s0; lr1 = lr1 * a1 + s1;
        mr0 = mn0; mr1 = mn1;
#pragma unroll
        for (int g = 0; g < 16; ++g) {
            o[g][0] *= a0; o[g][1] *= a0; o[g][2] *= a1; o[g][3] *= a1;
        }

        // ---- O += P V: P A-frags built in-register from s (C-frag == A-frag) ----
#pragma unroll
        for (int kk = 0; kk < 4; ++kk) {
            const int ga = kk * 2, gb = ga + 1;
            uint32_t ph0 = pack_bf16(s[ga][0], s[ga][1]);
            uint32_t ph1 = pack_bf16(s[ga][2], s[ga][3]);
            uint32_t ph2 = pack_bf16(s[gb][0], s[gb][1]);
            uint32_t ph3 = pack_bf16(s[gb][2], s[gb][3]);
            uint32_t pl0 = pack_bf16(s[ga][0] - bf_lo(ph0), s[ga][1] - bf_hi(ph0));
            uint32_t pl1 = pack_bf16(s[ga][2] - bf_lo(ph1), s[ga][3] - bf_hi(ph1));
            uint32_t pl2 = pack_bf16(s[gb][0] - bf_lo(ph2), s[gb][1] - bf_hi(ph2));
            uint32_t pl3 = pack_bf16(s[gb][2] - bf_lo(ph3), s[gb][3] - bf_hi(ph3));
#pragma unroll
            for (int gp = 0; gp < 8; ++gp) {
                uint32_t vh0, vh1, vh2, vh3, vl0, vl1, vl2, vl3;
                ldsm4t(frag_addr(sb + SM_VHI, kk << 4, gp << 4, l), vh0, vh1, vh2, vh3);
                ldsm4t(frag_addr(sb + SM_VLO, kk << 4, gp << 4, l), vl0, vl1, vl2, vl3);
                mma16816(o[2 * gp],     ph0, ph1, ph2, ph3, vh0, vh1);
                mma16816(o[2 * gp],     ph0, ph1, ph2, ph3, vl0, vl1);
                mma16816(o[2 * gp],     pl0, pl1, pl2, pl3, vh0, vh1);
                mma16816(o[2 * gp + 1], ph0, ph1, ph2, ph3, vh2, vh3);
                mma16816(o[2 * gp + 1], ph0, ph1, ph2, ph3, vl2, vl3);
                mma16816(o[2 * gp + 1], pl0, pl1, pl2, pl3, vh2, vh3);
            }
        }
    }

    // ---- epilogue: divide by (l + 1e-6), store [c][m] ----
    const float i0 = 1.0f / (lr0 + 1e-6f);
    const float i1 = 1.0f / (lr1 + 1e-6f);
    float* ob = out + bCN + m0 + (w << 4);
#pragma unroll
    for (int g = 0; g < 16; ++g) {
        const int c = (g << 3) + qc;
        ob[(size_t)c * NSEQ + qr]           = o[g][0] * i0;
        ob[(size_t)(c + 1) * NSEQ + qr]     = o[g][1] * i0;
        ob[(size_t)c * NSEQ + qr + 8]       = o[g][2] * i1;
        ob[(size_t)(c + 1) * NSEQ + qr + 8] = o[g][3] * i1;
    }
}

extern "C" void kernel_launch(void* const* d_in, const int* in_sizes, int n_in,
                              void* d_out, int out_size)
{
    const float* key   = (const float*)d_in[0];
    const float* mixin = (const float*)d_in[1];
    const float* query = (const float*)d_in[2];
    float* out = (float*)d_out;

    cudaFuncSetAttribute(attn_hmma_kernel,
                         cudaFuncAttributeMaxDynamicSharedMemorySize, SMEM_BYTES);
    attn_hmma_kernel<<<256, 256, SMEM_BYTES>>>(key, mixin, query, out);
}

// round 5
// speedup vs baseline: 2.5763x; 1.0039x over previous
#include <cuda_runtime.h>
#include <cuda_bf16.h>
#include <cstdint>

// causal_attention: B=8, N=4096, d=128, fp32 [B,C,N] channel-major in/out.
// HMMA (mma.sync m16n8k16 bf16) flash attention, fp32 via bf16 hi/lo split.
// R5: MMA issue reordered so consecutive MMAs hit different accumulators
// (split terms as rounds over 8 independent accumulators) -> rt-bound not
// latency-bound tensor pipe.

constexpr int NSEQ = 4096;
constexpr int CDIM = 128;

constexpr int SM_QHI = 0;          // 128 x 128 bf16 (32KB)
constexpr int SM_QLO = 32768;
constexpr int SM_KHI = 65536;      // 64 x 128 bf16 (16KB)
constexpr int SM_KLO = 81920;
constexpr int SM_VHI = 98304;
constexpr int SM_VLO = 114688;
constexpr int SMEM_BYTES = 131072;

// 1/sqrt(128) * log2(e)
#define SCL 0.12751744955161f

__device__ __forceinline__ uint32_t su32(const void* p) {
    uint32_t a;
    asm("{ .reg .u64 t; cvta.to.shared.u64 t, %1; cvt.u32.u64 %0, t; }" : "=r"(a) : "l"(p));
    return a;
}

__device__ __forceinline__ uint32_t pack_bf16(float a, float b) {
    uint32_t r;
    asm("cvt.rn.bf16x2.f32 %0, %1, %2;" : "=r"(r) : "f"(b), "f"(a));
    return r;
}
__device__ __forceinline__ float bf_lo(uint32_t u) { return __uint_as_float(u << 16); }
__device__ __forceinline__ float bf_hi(uint32_t u) { return __uint_as_float(u & 0xffff0000u); }

__device__ __forceinline__ void ldsm4(uint32_t addr, uint32_t* r) {
    asm volatile("ldmatrix.sync.aligned.m8n8.x4.shared.b16 {%0,%1,%2,%3}, [%4];"
                 : "=r"(r[0]), "=r"(r[1]), "=r"(r[2]), "=r"(r[3]) : "r"(addr));
}
__device__ __forceinline__ void ldsm4t(uint32_t addr, uint32_t* r) {
    asm volatile("ldmatrix.sync.aligned.m8n8.x4.trans.shared.b16 {%0,%1,%2,%3}, [%4];"
                 : "=r"(r[0]), "=r"(r[1]), "=r"(r[2]), "=r"(r[3]) : "r"(addr));
}

__device__ __forceinline__ void mma16816(float* d, const uint32_t* a,
                                         uint32_t b0, uint32_t b1) {
    asm volatile(
        "mma.sync.aligned.m16n8k16.row.col.f32.bf16.bf16.f32 "
        "{%0,%1,%2,%3}, {%4,%5,%6,%7}, {%8,%9}, {%0,%1,%2,%3};"
        : "+f"(d[0]), "+f"(d[1]), "+f"(d[2]), "+f"(d[3])
        : "r"(a[0]), "r"(a[1]), "r"(a[2]), "r"(a[3]), "r"(b0), "r"(b1));
}

// per-lane ldmatrix.x4 address covering a 16-row x 16-col bf16 region.
__device__ __forceinline__ uint32_t frag_addr(uint32_t base, int rb, int cb, int l) {
    int row = rb + (l & 7) + ((l >> 3) & 1) * 8;
    int col = cb + ((l >> 4) << 3);
    return base + (row << 8) + ((((col >> 3) ^ (row & 7)) << 4));
}

// gmem fp32 [c][token] -> smem bf16 hi/lo [row][c], swizzled, R rows.
template <int R>
__device__ __forceinline__ void fill_tile(char* smem, int hi_off, int lo_off,
                                          const float* gsrc, int tok0, int tid) {
    constexpr int SH = (R == 128) ? 7 : 6;
    for (int it = tid; it < R * 16; it += 256) {
        const int r  = it & (R - 1);
        const int c8 = (it >> SH) << 3;
        const float* g = gsrc + (size_t)c8 * NSEQ + tok0 + r;
        uint32_t hi[4], lo[4];
#pragma unroll
        for (int p = 0; p < 4; ++p) {
            float a = g[(size_t)(2 * p) * NSEQ];
            float c = g[(size_t)(2 * p + 1) * NSEQ];
            uint32_t h = pack_bf16(a, c);
            hi[p] = h;
            lo[p] = pack_bf16(a - bf_lo(h), c - bf_hi(h));
        }
        const int off = (r << 8) + ((((c8 >> 3) ^ (r & 7)) << 4));
        *(uint4*)(smem + hi_off + off) = make_uint4(hi[0], hi[1], hi[2], hi[3]);
        *(uint4*)(smem + lo_off + off) = make_uint4(lo[0], lo[1], lo[2], lo[3]);
    }
}

__global__ __launch_bounds__(256, 1)
void attn_hmma_kernel(const float* __restrict__ key,
                      const float* __restrict__ mixin,
                      const float* __restrict__ query,
                      float* __restrict__ out)
{
    extern __shared__ char smem[];
    const uint32_t sb = su32(smem);

    const int tid = threadIdx.x;
    const int l   = tid & 31;
    const int w   = tid >> 5;

    const int bx = blockIdx.x;
    const int qt = 31 - (bx >> 3);
    const int b  = bx & 7;
    const int m0 = qt * 128;

    const size_t bCN = (size_t)b * CDIM * NSEQ;

    fill_tile<128>(smem, SM_QHI, SM_QLO, query + bCN, m0, tid);

    const int qr  = l >> 2;
    const int qc  = (l & 3) << 1;
    const int ig0 = m0 + (w << 4) + qr;
    const int ig1 = ig0 + 8;

    float o[16][4];
#pragma unroll
    for (int g = 0; g < 16; ++g)
#pragma unroll
        for (int e = 0; e < 4; ++e) o[g][e] = 0.0f;
    float mr0 = -3.0e38f, mr1 = -3.0e38f, lr0 = 0.0f, lr1 = 0.0f;

    const int nkt = qt * 2 + 2;

    for (int kt = 0; kt < nkt; ++kt) {
        const int j0 = kt * 64;

        __syncthreads();
        fill_tile<64>(smem, SM_KHI, SM_KLO, key + bCN, j0, tid);
        fill_tile<64>(smem, SM_VHI, SM_VLO, mixin + bCN, j0, tid);
        __syncthreads();

        // ---- S = Q K^T: 3 rounds x 8 independent accumulators per k-chunk ----
        float s[8][4];
#pragma unroll
        for (int g = 0; g < 8; ++g)
#pragma unroll
            for (int e = 0; e < 4; ++e) s[g][e] = 0.0f;

#pragma unroll
        for (int ck = 0; ck < 8; ++ck) {
            uint32_t ah[4], al[4];
            ldsm4(frag_addr(sb + SM_QHI, w << 4, ck << 4, l), ah);
            ldsm4(frag_addr(sb + SM_QLO, w << 4, ck << 4, l), al);
            uint32_t kh[4][4], kl[4][4];
#pragma unroll
            for (int g2 = 0; g2 < 4; ++g2) {
                ldsm4(frag_addr(sb + SM_KHI, g2 << 4, ck << 4, l), kh[g2]);
                ldsm4(frag_addr(sb + SM_KLO, g2 << 4, ck << 4, l), kl[g2]);
            }
            // round 1: hi*hi (8 independent MMAs)
#pragma unroll
            for (int g2 = 0; g2 < 4; ++g2) {
                mma16816(s[2 * g2],     ah, kh[g2][0], kh[g2][2]);
                mma16816(s[2 * g2 + 1], ah, kh[g2][1], kh[g2][3]);
            }
            // round 2: hi*lo
#pragma unroll
            for (int g2 = 0; g2 < 4; ++g2) {
                mma16816(s[2 * g2],     ah, kl[g2][0], kl[g2][2]);
                mma16816(s[2 * g2 + 1], ah, kl[g2][1], kl[g2][3]);
            }
            // round 3: lo*hi
#pragma unroll
            for (int g2 = 0; g2 < 4; ++g2) {
                mma16816(s[2 * g2],     al, kh[g2][0], kh[g2][2]);
                mma16816(s[2 * g2 + 1], al, kh[g2][1], kh[g2][3]);
            }
        }

        // ---- online softmax ----
        const bool tm = (j0 + 63 >= m0 + (w << 4));
        if (tm) {
#pragma unroll
            for (int g = 0; g < 8; ++g) {
                const int jg = j0 + (g << 3) + qc;
                if (jg     >= ig0) s[g][0] = -1.0e10f;
                if (jg + 1 >= ig0) s[g][1] = -1.0e10f;
                if (jg     >= ig1) s[g][2] = -1.0e10f;
                if (jg + 1 >= ig1) s[g][3] = -1.0e10f;
            }
        }
        float mx0 = -3.0e38f, mx1 = -3.0e38f;
#pragma unroll
        for (int g = 0; g < 8; ++g) {
            mx0 = fmaxf(mx0, fmaxf(s[g][0], s[g][1]));
            mx1 = fmaxf(mx1, fmaxf(s[g][2], s[g][3]));
        }
        mx0 = fmaxf(mx0, __shfl_xor_sync(0xffffffffu, mx0, 1, 32));
        mx0 = fmaxf(mx0, __shfl_xor_sync(0xffffffffu, mx0, 2, 32));
        mx1 = fmaxf(mx1, __shfl_xor_sync(0xffffffffu, mx1, 1, 32));
        mx1 = fmaxf(mx1, __shfl_xor_sync(0xffffffffu, mx1, 2, 32));

        const float mn0 = fmaxf(mr0, mx0), mn1 = fmaxf(mr1, mx1);
        const float a0  = exp2f((mr0 - mn0) * SCL);
        const float a1  = exp2f((mr1 - mn1) * SCL);

        float s0 = 0.0f, s1 = 0.0f;
#pragma unroll
        for (int g = 0; g < 8; ++g) {
#pragma unroll
            for (int e = 0; e < 2; ++e) {
                const int jg = j0 + (g << 3) + qc + e;
                float p0 = (tm && jg >= ig0) ? 0.0f : exp2f((s[g][e] - mn0) * SCL);
                float p1 = (tm && jg >= ig1) ? 0.0f : exp2f((s[g][2 + e] - mn1) * SCL);
                s[g][e] = p0; s[g][2 + e] = p1;
                s0 += p0; s1 += p1;
            }
        }
        s0 += __shfl_xor_sync(0xffffffffu, s0, 1, 32);
        s0 += __shfl_xor_sync(0xffffffffu, s0, 2, 32);
        s1 += __shfl_xor_sync(0xffffffffu, s1, 1, 32);
        s1 += __shfl_xor_sync(0xffffffffu, s1, 2, 32);

        lr0 = lr0 * a0 + s0; lr1 = lr1 * a1 + s1;
        mr0 = mn0; mr1 = mn1;
#pragma unroll
        for (int g = 0; g < 16; ++g) {
            o[g][0] *= a0; o[g][1] *= a0; o[g][2] *= a1; o[g][3] *= a1;
        }

        // ---- O += P V: per kk, per 4-gp chunk, 3 rounds x 8 independent MMAs ----
#pragma unroll
        for (int kk = 0; kk < 4; ++kk) {
            const int ga = kk * 2, gb = ga + 1;
            uint32_t ph[4], pl[4];
            ph[0] = pack_bf16(s[ga][0], s[ga][1]);
            ph[1] = pack_bf16(s[ga][2], s[ga][3]);
            ph[2] = pack_bf16(s[gb][0], s[gb][1]);
            ph[3] = pack_bf16(s[gb][2], s[gb][3]);
            pl[0] = pack_bf16(s[ga][0] - bf_lo(ph[0]), s[ga][1] - bf_hi(ph[0]));
            pl[1] = pack_bf16(s[ga][2] - bf_lo(ph[1]), s[ga][3] - bf_hi(ph[1]));
            pl[2] = pack_bf16(s[gb][0] - bf_lo(ph[2]), s[gb][1] - bf_hi(ph[2]));
            pl[3] = pack_bf16(s[gb][2] - bf_lo(ph[3]), s[gb][3] - bf_hi(ph[3]));
#pragma unroll
            for (int hc = 0; hc < 2; ++hc) {
                uint32_t vh[4][4], vl[4][4];
#pragma unroll
                for (int i = 0; i < 4; ++i) {
                    const int gp = hc * 4 + i;
                    ldsm4t(frag_addr(sb + SM_VHI, kk << 4, gp << 4, l), vh[i]);
                    ldsm4t(frag_addr(sb + SM_VLO, kk << 4, gp << 4, l), vl[i]);
                }
                // round 1: ph * vh
#pragma unroll
                for (int i = 0; i < 4; ++i) {
                    const int gp = hc * 4 + i;
                    mma16816(o[2 * gp],     ph, vh[i][0], vh[i][1]);
                    mma16816(o[2 * gp + 1], ph, vh[i][2], vh[i][3]);
                }
                // round 2: ph * vl
#pragma unroll
                for (int i = 0; i < 4; ++i) {
                    const int gp = hc * 4 + i;
                    mma16816(o[2 * gp],     ph, vl[i][0], vl[i][1]);
                    mma16816(o[2 * gp + 1], ph, vl[i][2], vl[i][3]);
                }
                // round 3: pl * vh
#pragma unroll
                for (int i = 0; i < 4; ++i) {
                    const int gp = hc * 4 + i;
                    mma16816(o[2 * gp],     pl, vh[i][0], vh[i][1]);
                    mma16816(o[2 * gp + 1], pl, vh[i][2], vh[i][3]);
                }
            }
        }
    }

    // ---- epilogue ----
    const float i0 = 1.0f / (lr0 + 1e-6f);
    const float i1 = 1.0f / (lr1 + 1e-6f);
    float* ob = out + bCN + m0 + (w << 4);
#pragma unroll
    for (int g = 0; g < 16; ++g) {
        const int c = (g << 3) + qc;
        ob[(size_t)c * NSEQ + qr]           = o[g][0] * i0;
        ob[(size_t)(c + 1) * NSEQ + qr]     = o[g][1] * i0;
        ob[(size_t)c * NSEQ + qr + 8]       = o[g][2] * i1;
        ob[(size_t)(c + 1) * NSEQ + qr + 8] = o[g][3] * i1;
    }
}

extern "C" void kernel_launch(void* const* d_in, const int* in_sizes, int n_in,
                              void* d_out, int out_size)
{
    const float* key   = (const float*)d_in[0];
    const float* mixin = (const float*)d_in[1];
    const float* query = (const float*)d_in[2];
    float* out = (float*)d_out;

    cudaFuncSetAttribute(attn_hmma_kernel,
                         cudaFuncAttributeMaxDynamicSharedMemorySize, SMEM_BYTES);
    attn_hmma_kernel<<<256, 256, SMEM_BYTES>>>(key, mixin, query, out);
}

// round 6
// speedup vs baseline: 2.7118x; 1.0526x over previous
#include <cuda_runtime.h>
#include <cuda_bf16.h>
#include <cstdint>

// causal_attention: B=8, N=4096, d=128, fp32 [B,C,N] channel-major in/out.
// HMMA (mma.sync m16n8k16 bf16) flash attention, fp32 via bf16 hi/lo split.
// R6: 512 threads / 16 warps. Warp pairs (p, half): S split by j-half,
// PV split by c-half, P exchanged via smem. Same total MMA work, 2x warps
// per SMSP for latency hiding.

constexpr int NSEQ = 4096;
constexpr int CDIM = 128;
constexpr int NTHR = 512;

constexpr int SM_QHI  = 0;          // 128 x 128 bf16 (32KB)
constexpr int SM_QLO  = 32768;
constexpr int SM_KHI  = 65536;      // 64 x 128 bf16 (16KB)
constexpr int SM_KLO  = 81920;
constexpr int SM_VHI  = 98304;
constexpr int SM_VLO  = 114688;
constexpr int SM_PHI  = 131072;     // 128 x 64 bf16 (16KB), 128B rows
constexpr int SM_PLO  = 147456;
constexpr int SM_RMAX = 163840;     // 2 x 128 floats
constexpr int SM_RSUM = 164864;     // 2 x 128 floats
constexpr int SMEM_BYTES = 165888;

// 1/sqrt(128) * log2(e)
#define SCL 0.12751744955161f

__device__ __forceinline__ uint32_t su32(const void* p) {
    uint32_t a;
    asm("{ .reg .u64 t; cvta.to.shared.u64 t, %1; cvt.u32.u64 %0, t; }" : "=r"(a) : "l"(p));
    return a;
}
__device__ __forceinline__ uint32_t pack_bf16(float a, float b) {
    uint32_t r;
    asm("cvt.rn.bf16x2.f32 %0, %1, %2;" : "=r"(r) : "f"(b), "f"(a));
    return r;
}
__device__ __forceinline__ float bf_lo(uint32_t u) { return __uint_as_float(u << 16); }
__device__ __forceinline__ float bf_hi(uint32_t u) { return __uint_as_float(u & 0xffff0000u); }

__device__ __forceinline__ void ldsm4(uint32_t addr, uint32_t* r) {
    asm volatile("ldmatrix.sync.aligned.m8n8.x4.shared.b16 {%0,%1,%2,%3}, [%4];"
                 : "=r"(r[0]), "=r"(r[1]), "=r"(r[2]), "=r"(r[3]) : "r"(addr));
}
__device__ __forceinline__ void ldsm4t(uint32_t addr, uint32_t* r) {
    asm volatile("ldmatrix.sync.aligned.m8n8.x4.trans.shared.b16 {%0,%1,%2,%3}, [%4];"
                 : "=r"(r[0]), "=r"(r[1]), "=r"(r[2]), "=r"(r[3]) : "r"(addr));
}
__device__ __forceinline__ void mma16816(float* d, const uint32_t* a,
                                         uint32_t b0, uint32_t b1) {
    asm volatile(
        "mma.sync.aligned.m16n8k16.row.col.f32.bf16.bf16.f32 "
        "{%0,%1,%2,%3}, {%4,%5,%6,%7}, {%8,%9}, {%0,%1,%2,%3};"
        : "+f"(d[0]), "+f"(d[1]), "+f"(d[2]), "+f"(d[3])
        : "r"(a[0]), "r"(a[1]), "r"(a[2]), "r"(a[3]), "r"(b0), "r"(b1));
}

// ldmatrix.x4 lane address: 16x16 bf16 region, 256B row stride (Q/K/V tiles).
__device__ __forceinline__ uint32_t frag_addr(uint32_t base, int rb, int cb, int l) {
    int row = rb + (l & 7) + ((l >> 3) & 1) * 8;
    int col = cb + ((l >> 4) << 3);
    return base + (row << 8) + ((((col >> 3) ^ (row & 7)) << 4));
}
// same for the P tile: 128B row stride (64 bf16 cols).
__device__ __forceinline__ uint32_t frag_addr_p(uint32_t base, int rb, int cb, int l) {
    int row = rb + (l & 7) + ((l >> 3) & 1) * 8;
    int col = cb + ((l >> 4) << 3);
    return base + (row << 7) + ((((col >> 3) ^ (row & 7)) << 4));
}

// gmem fp32 [c][token] -> smem bf16 hi/lo [row][c], swizzled, R rows.
template <int R>
__device__ __forceinline__ void fill_tile(char* smem, int hi_off, int lo_off,
                                          const float* gsrc, int tok0, int tid) {
    constexpr int SH = (R == 128) ? 7 : 6;
    for (int it = tid; it < R * 16; it += NTHR) {
        const int r  = it & (R - 1);
        const int c8 = (it >> SH) << 3;
        const float* g = gsrc + (size_t)c8 * NSEQ + tok0 + r;
        uint32_t hi[4], lo[4];
#pragma unroll
        for (int q = 0; q < 4; ++q) {
            float a = g[(size_t)(2 * q) * NSEQ];
            float c = g[(size_t)(2 * q + 1) * NSEQ];
            uint32_t h = pack_bf16(a, c);
            hi[q] = h;
            lo[q] = pack_bf16(a - bf_lo(h), c - bf_hi(h));
        }
        const int off = (r << 8) + ((((c8 >> 3) ^ (r & 7)) << 4));
        *(uint4*)(smem + hi_off + off) = make_uint4(hi[0], hi[1], hi[2], hi[3]);
        *(uint4*)(smem + lo_off + off) = make_uint4(lo[0], lo[1], lo[2], lo[3]);
    }
}

__global__ __launch_bounds__(NTHR, 1)
void attn_hmma_kernel(const float* __restrict__ key,
                      const float* __restrict__ mixin,
                      const float* __restrict__ query,
                      float* __restrict__ out)
{
    extern __shared__ char smem[];
    const uint32_t sb = su32(smem);

    const int tid  = threadIdx.x;
    const int l    = tid & 31;
    const int w    = tid >> 5;
    const int p    = w & 7;    // pair: q-rows 16p..16p+15
    const int half = w >> 3;   // 0: j 0-31 / c 0-63,  1: j 32-63 / c 64-127

    const int bx = blockIdx.x;
    const int qt = 31 - (bx >> 3);
    const int b  = bx & 7;
    const int m0 = qt * 128;

    const size_t bCN = (size_t)b * CDIM * NSEQ;

    fill_tile<128>(smem, SM_QHI, SM_QLO, query + bCN, m0, tid);

    const int qr   = l >> 2;
    const int qc   = (l & 3) << 1;
    const int row0 = (p << 4) + qr;     // within-tile row
    const int row1 = row0 + 8;
    const int ig0  = m0 + row0;
    const int ig1  = m0 + row1;

    float o[8][4];
#pragma unroll
    for (int g = 0; g < 8; ++g)
#pragma unroll
        for (int e = 0; e < 4; ++e) o[g][e] = 0.0f;
    float mr0 = -3.0e38f, mr1 = -3.0e38f, lr0 = 0.0f, lr1 = 0.0f;

    float* rmax = (float*)(smem + SM_RMAX);
    float* rsum = (float*)(smem + SM_RSUM);

    const int nkt = qt * 2 + 2;

    for (int kt = 0; kt < nkt; ++kt) {
        const int j0 = kt * 64;

        __syncthreads();   // previous PV done reading K/V/P
        fill_tile<64>(smem, SM_KHI, SM_KLO, key + bCN, j0, tid);
        fill_tile<64>(smem, SM_VHI, SM_VLO, mixin + bCN, j0, tid);
        __syncthreads();

        // ---- S (warp's j-half): s[4][4], rows (qr,qr+8), j = 32*half+8g+qc+{0,1} ----
        float s[4][4];
#pragma unroll
        for (int g = 0; g < 4; ++g)
#pragma unroll
            for (int e = 0; e < 4; ++e) s[g][e] = 0.0f;

#pragma unroll
        for (int ck = 0; ck < 8; ++ck) {
            uint32_t ah[4], al[4];
            ldsm4(frag_addr(sb + SM_QHI, p << 4, ck << 4, l), ah);
            ldsm4(frag_addr(sb + SM_QLO, p << 4, ck << 4, l), al);
            uint32_t kh[2][4], kl[2][4];
#pragma unroll
            for (int g2 = 0; g2 < 2; ++g2) {
                const int jb = ((half << 1) + g2) << 4;
                ldsm4(frag_addr(sb + SM_KHI, jb, ck << 4, l), kh[g2]);
                ldsm4(frag_addr(sb + SM_KLO, jb, ck << 4, l), kl[g2]);
            }
#pragma unroll
            for (int g2 = 0; g2 < 2; ++g2) {
                mma16816(s[2 * g2],     ah, kh[g2][0], kh[g2][2]);
                mma16816(s[2 * g2 + 1], ah, kh[g2][1], kh[g2][3]);
            }
#pragma unroll
            for (int g2 = 0; g2 < 2; ++g2) {
                mma16816(s[2 * g2],     ah, kl[g2][0], kl[g2][2]);
                mma16816(s[2 * g2 + 1], ah, kl[g2][1], kl[g2][3]);
            }
#pragma unroll
            for (int g2 = 0; g2 < 2; ++g2) {
                mma16816(s[2 * g2],     al, kh[g2][0], kh[g2][2]);
                mma16816(s[2 * g2 + 1], al, kh[g2][1], kh[g2][3]);
            }
        }

        // ---- softmax: mask, warp-half max, cross-pair via smem ----
        const int jb0 = j0 + (half << 5);
        const bool tm = (jb0 + 31 >= m0 + (p << 4));
        if (tm) {
#pragma unroll
            for (int g = 0; g < 4; ++g) {
                const int jg = jb0 + (g << 3) + qc;
                if (jg     >= ig0) s[g][0] = -1.0e10f;
                if (jg + 1 >= ig0) s[g][1] = -1.0e10f;
                if (jg     >= ig1) s[g][2] = -1.0e10f;
                if (jg + 1 >= ig1) s[g][3] = -1.0e10f;
            }
        }
        float mx0 = -3.0e38f, mx1 = -3.0e38f;
#pragma unroll
        for (int g = 0; g < 4; ++g) {
            mx0 = fmaxf(mx0, fmaxf(s[g][0], s[g][1]));
            mx1 = fmaxf(mx1, fmaxf(s[g][2], s[g][3]));
        }
        mx0 = fmaxf(mx0, __shfl_xor_sync(0xffffffffu, mx0, 1, 32));
        mx0 = fmaxf(mx0, __shfl_xor_sync(0xffffffffu, mx0, 2, 32));
        mx1 = fmaxf(mx1, __shfl_xor_sync(0xffffffffu, mx1, 1, 32));
        mx1 = fmaxf(mx1, __shfl_xor_sync(0xffffffffu, mx1, 2, 32));
        if ((l & 3) == 0) {
            rmax[(half << 7) + row0] = mx0;
            rmax[(half << 7) + row1] = mx1;
        }
        __syncthreads();

        const float rm0 = fmaxf(rmax[row0], rmax[128 + row0]);
        const float rm1 = fmaxf(rmax[row1], rmax[128 + row1]);
        const float mn0 = fmaxf(mr0, rm0), mn1 = fmaxf(mr1, rm1);
        const float a0  = exp2f((mr0 - mn0) * SCL);
        const float a1  = exp2f((mr1 - mn1) * SCL);

        float s0 = 0.0f, s1 = 0.0f;
#pragma unroll
        for (int g = 0; g < 4; ++g) {
#pragma unroll
            for (int e = 0; e < 2; ++e) {
                const int jg = jb0 + (g << 3) + qc + e;
                float p0 = (tm && jg >= ig0) ? 0.0f : exp2f((s[g][e] - mn0) * SCL);
                float p1 = (tm && jg >= ig1) ? 0.0f : exp2f((s[g][2 + e] - mn1) * SCL);
                s[g][e] = p0; s[g][2 + e] = p1;
                s0 += p0; s1 += p1;
            }
        }
        s0 += __shfl_xor_sync(0xffffffffu, s0, 1, 32);
        s0 += __shfl_xor_sync(0xffffffffu, s0, 2, 32);
        s1 += __shfl_xor_sync(0xffffffffu, s1, 1, 32);
        s1 += __shfl_xor_sync(0xffffffffu, s1, 2, 32);
        if ((l & 3) == 0) {
            rsum[(half << 7) + row0] = s0;
            rsum[(half << 7) + row1] = s1;
        }

        // ---- stage P hi/lo (warp's j-half) to smem, swizzled 128B rows ----
#pragma unroll
        for (int g = 0; g < 4; ++g) {
            const int colb = (((half << 5) + (g << 3) + qc)) << 1;  // byte col
            uint32_t hw0 = pack_bf16(s[g][0], s[g][1]);
            uint32_t lw0 = pack_bf16(s[g][0] - bf_lo(hw0), s[g][1] - bf_hi(hw0));
            const int off0 = (row0 << 7) + (((colb >> 4) ^ (row0 & 7)) << 4) + (colb & 15);
            *(uint32_t*)(smem + SM_PHI + off0) = hw0;
            *(uint32_t*)(smem + SM_PLO + off0) = lw0;
            uint32_t hw1 = pack_bf16(s[g][2], s[g][3]);
            uint32_t lw1 = pack_bf16(s[g][2] - bf_lo(hw1), s[g][3] - bf_hi(hw1));
            const int off1 = (row1 << 7) + (((colb >> 4) ^ (row1 & 7)) << 4) + (colb & 15);
            *(uint32_t*)(smem + SM_PHI + off1) = hw1;
            *(uint32_t*)(smem + SM_PLO + off1) = lw1;
        }
        __syncthreads();   // P + rsum ready

        const float t0 = rsum[row0] + rsum[128 + row0];
        const float t1 = rsum[row1] + rsum[128 + row1];
        lr0 = lr0 * a0 + t0; lr1 = lr1 * a1 + t1;
        mr0 = mn0; mr1 = mn1;
#pragma unroll
        for (int g = 0; g < 8; ++g) {
            o[g][0] *= a0; o[g][1] *= a0; o[g][2] *= a1; o[g][3] *= a1;
        }

        // ---- O += P V (full j, warp's c-half) ----
#pragma unroll
        for (int kk = 0; kk < 4; ++kk) {
            uint32_t pah[4], pal[4];
            ldsm4(frag_addr_p(sb + SM_PHI, p << 4, kk << 4, l), pah);
            ldsm4(frag_addr_p(sb + SM_PLO, p << 4, kk << 4, l), pal);
            uint32_t vh[4][4], vl[4][4];
#pragma unroll
            for (int i = 0; i < 4; ++i) {
                const int gp = (half << 2) + i;
                ldsm4t(frag_addr(sb + SM_VHI, kk << 4, gp << 4, l), vh[i]);
                ldsm4t(frag_addr(sb + SM_VLO, kk << 4, gp << 4, l), vl[i]);
            }
#pragma unroll
            for (int i = 0; i < 4; ++i) {
                mma16816(o[2 * i],     pah, vh[i][0], vh[i][1]);
                mma16816(o[2 * i + 1], pah, vh[i][2], vh[i][3]);
            }
#pragma unroll
            for (int i = 0; i < 4; ++i) {
                mma16816(o[2 * i],     pah, vl[i][0], vl[i][1]);
                mma16816(o[2 * i + 1], pah, vl[i][2], vl[i][3]);
            }
#pragma unroll
            for (int i = 0; i < 4; ++i) {
                mma16816(o[2 * i],     pal, vh[i][0], vh[i][1]);
                mma16816(o[2 * i + 1], pal, vh[i][2], vh[i][3]);
            }
        }
    }

    // ---- epilogue ----
    const float i0 = 1.0f / (lr0 + 1e-6f);
    const float i1 = 1.0f / (lr1 + 1e-6f);
    float* ob = out + bCN + m0 + (p << 4);
#pragma unroll
    for (int g = 0; g < 8; ++g) {
        const int c = (half << 6) + (g << 3) + qc;
        ob[(size_t)c * NSEQ + qr]           = o[g][0] * i0;
        ob[(size_t)(c + 1) * NSEQ + qr]     = o[g][1] * i0;
        ob[(size_t)c * NSEQ + qr + 8]       = o[g][2] * i1;
        ob[(size_t)(c + 1) * NSEQ + qr + 8] = o[g][3] * i1;
    }
}

extern "C" void kernel_launch(void* const* d_in, const int* in_sizes, int n_in,
                              void* d_out, int out_size)
{
    const float* key   = (const float*)d_in[0];
    const float* mixin = (const float*)d_in[1];
    const float* query = (const float*)d_in[2];
    float* out = (float*)d_out;

    cudaFuncSetAttribute(attn_hmma_kernel,
                         cudaFuncAttributeMaxDynamicSharedMemorySize, SMEM_BYTES);
    attn_hmma_kernel<<<256, NTHR, SMEM_BYTES>>>(key, mixin, query, out);
}

// round 7
// speedup vs baseline: 2.9734x; 1.0965x over previous
#include <cuda_runtime.h>
#include <cuda_bf16.h>
#include <cstdint>

// causal_attention: B=8, N=4096, d=128, fp32 [B,C,N] channel-major in/out.
// HMMA bf16 hi/lo-split flash attention.
// R7: cp.async-staged K/V (raw fp32 smem buffer, prefetch next tile during
// compute) + pair-scoped named barriers for softmax/P exchange.

constexpr int NSEQ = 4096;
constexpr int CDIM = 128;
constexpr int NTHR = 512;

constexpr int SM_RAWK = 0;          // 128 x 64 fp32 raw (32KB), 256B rows
constexpr int SM_RAWV = 32768;
constexpr int SM_QHI  = 65536;      // 128 x 128 bf16 (32KB), 256B rows, swizzled
constexpr int SM_QLO  = 98304;
constexpr int SM_KHI  = 131072;     // 64 x 128 bf16 (16KB)
constexpr int SM_KLO  = 147456;
constexpr int SM_VHI  = 163840;
constexpr int SM_VLO  = 180224;
constexpr int SM_PHI  = 196608;     // 128 x 64 bf16 (16KB), 128B rows
constexpr int SM_PLO  = 212992;
constexpr int SM_RMAX = 229376;     // 2 x 128 floats
constexpr int SM_RSUM = 230400;
constexpr int SMEM_BYTES = 231424;  // 226KB

// 1/sqrt(128) * log2(e)
#define SCL 0.12751744955161f

__device__ __forceinline__ uint32_t su32(const void* p) {
    uint32_t a;
    asm("{ .reg .u64 t; cvta.to.shared.u64 t, %1; cvt.u32.u64 %0, t; }" : "=r"(a) : "l"(p));
    return a;
}
__device__ __forceinline__ uint32_t pack_bf16(float a, float b) {
    uint32_t r;
    asm("cvt.rn.bf16x2.f32 %0, %1, %2;" : "=r"(r) : "f"(b), "f"(a));
    return r;
}
__device__ __forceinline__ float bf_lo(uint32_t u) { return __uint_as_float(u << 16); }
__device__ __forceinline__ float bf_hi(uint32_t u) { return __uint_as_float(u & 0xffff0000u); }

__device__ __forceinline__ void ldsm4(uint32_t addr, uint32_t* r) {
    asm volatile("ldmatrix.sync.aligned.m8n8.x4.shared.b16 {%0,%1,%2,%3}, [%4];"
                 : "=r"(r[0]), "=r"(r[1]), "=r"(r[2]), "=r"(r[3]) : "r"(addr));
}
__device__ __forceinline__ void ldsm4t(uint32_t addr, uint32_t* r) {
    asm volatile("ldmatrix.sync.aligned.m8n8.x4.trans.shared.b16 {%0,%1,%2,%3}, [%4];"
                 : "=r"(r[0]), "=r"(r[1]), "=r"(r[2]), "=r"(r[3]) : "r"(addr));
}
__device__ __forceinline__ void mma16816(float* d, const uint32_t* a,
                                         uint32_t b0, uint32_t b1) {
    asm volatile(
        "mma.sync.aligned.m16n8k16.row.col.f32.bf16.bf16.f32 "
        "{%0,%1,%2,%3}, {%4,%5,%6,%7}, {%8,%9}, {%0,%1,%2,%3};"
        : "+f"(d[0]), "+f"(d[1]), "+f"(d[2]), "+f"(d[3])
        : "r"(a[0]), "r"(a[1]), "r"(a[2]), "r"(a[3]), "r"(b0), "r"(b1));
}

__device__ __forceinline__ void cp16(uint32_t saddr, const void* g) {
    asm volatile("cp.async.cg.shared.global [%0], [%1], 16;" :: "r"(saddr), "l"(g));
}
#define CP_COMMIT() asm volatile("cp.async.commit_group;" ::: "memory")
#define CP_WAIT0()  asm volatile("cp.async.wait_group 0;" ::: "memory")
#define BARP(id)    asm volatile("bar.sync %0, 64;" :: "r"(id) : "memory")

// ldmatrix.x4 lane address: 16x16 bf16 region, 256B row stride.
__device__ __forceinline__ uint32_t frag_addr(uint32_t base, int rb, int cb, int l) {
    int row = rb + (l & 7) + ((l >> 3) & 1) * 8;
    int col = cb + ((l >> 4) << 3);
    return base + (row << 8) + ((((col >> 3) ^ (row & 7)) << 4));
}
// P tile: 128B row stride.
__device__ __forceinline__ uint32_t frag_addr_p(uint32_t base, int rb, int cb, int l) {
    int row = rb + (l & 7) + ((l >> 3) & 1) * 8;
    int col = cb + ((l >> 4) << 3);
    return base + (row << 7) + ((((col >> 3) ^ (row & 7)) << 4));
}

// issue cp.async for one K/V tile (raw fp32) and commit.
__device__ __forceinline__ void prefetch_kv(uint32_t sbi, const float* kptr,
                                            const float* vptr, int j0, int tid) {
#pragma unroll
    for (int q = 0; q < 4; ++q) {
        const int idx = tid + q * NTHR;       // 0..2047
        const int c   = idx >> 4;
        const int off = (idx & 15) << 4;      // byte offset in 256B row
        cp16(sbi + SM_RAWK + (c << 8) + off,
             (const char*)(kptr + (size_t)c * NSEQ + j0) + off);
        cp16(sbi + SM_RAWV + (c << 8) + off,
             (const char*)(vptr + (size_t)c * NSEQ + j0) + off);
    }
    CP_COMMIT();
}

// raw fp32 smem [c][64] -> bf16 hi/lo smem [row=token][c], swizzled 256B rows.
__device__ __forceinline__ void convert_tile(char* smem, int raw_off,
                                             int hi_off, int lo_off, int tid) {
    const float* raws = (const float*)(smem + raw_off);
    for (int it = tid; it < 64 * 16; it += NTHR) {
        const int r  = it & 63;
        const int c8 = (it >> 6) << 3;
        uint32_t hi[4], lo[4];
#pragma unroll
        for (int q = 0; q < 4; ++q) {
            float a = raws[(c8 + 2 * q) * 64 + r];
            float c = raws[(c8 + 2 * q + 1) * 64 + r];
            uint32_t h = pack_bf16(a, c);
            hi[q] = h;
            lo[q] = pack_bf16(a - bf_lo(h), c - bf_hi(h));
        }
        const int off = (r << 8) + ((((c8 >> 3) ^ (r & 7)) << 4));
        *(uint4*)(smem + hi_off + off) = make_uint4(hi[0], hi[1], hi[2], hi[3]);
        *(uint4*)(smem + lo_off + off) = make_uint4(lo[0], lo[1], lo[2], lo[3]);
    }
}

__global__ __launch_bounds__(NTHR, 1)
void attn_hmma_kernel(const float* __restrict__ key,
                      const float* __restrict__ mixin,
                      const float* __restrict__ query,
                      float* __restrict__ out)
{
    extern __shared__ char smem[];
    const uint32_t sb = su32(smem);

    const int tid  = threadIdx.x;
    const int l    = tid & 31;
    const int w    = tid >> 5;
    const int p    = w & 7;    // pair: q-rows 16p..16p+15
    const int half = w >> 3;   // 0: j 0-31 / c 0-63,  1: j 32-63 / c 64-127

    const int bx = blockIdx.x;
    const int qt = 31 - (bx >> 3);
    const int b  = bx & 7;
    const int m0 = qt * 128;

    const size_t bCN = (size_t)b * CDIM * NSEQ;
    const float* kptr = key + bCN;
    const float* vptr = mixin + bCN;

    // prefetch first K/V tile, then convert Q (LDG overlaps cp.async)
    prefetch_kv(sb, kptr, vptr, 0, tid);
    {
        const float* qptr = query + bCN + m0;
        for (int it = tid; it < 128 * 16; it += NTHR) {
            const int r  = it & 127;
            const int c8 = (it >> 7) << 3;
            const float* g = qptr + (size_t)c8 * NSEQ + r;
            uint32_t hi[4], lo[4];
#pragma unroll
            for (int q = 0; q < 4; ++q) {
                float a = g[(size_t)(2 * q) * NSEQ];
                float c = g[(size_t)(2 * q + 1) * NSEQ];
                uint32_t h = pack_bf16(a, c);
                hi[q] = h;
                lo[q] = pack_bf16(a - bf_lo(h), c - bf_hi(h));
            }
            const int off = (r << 8) + ((((c8 >> 3) ^ (r & 7)) << 4));
            *(uint4*)(smem + SM_QHI + off) = make_uint4(hi[0], hi[1], hi[2], hi[3]);
            *(uint4*)(smem + SM_QLO + off) = make_uint4(lo[0], lo[1], lo[2], lo[3]);
        }
    }

    const int qr   = l >> 2;
    const int qc   = (l & 3) << 1;
    const int row0 = (p << 4) + qr;
    const int row1 = row0 + 8;
    const int ig0  = m0 + row0;
    const int ig1  = m0 + row1;
    const int bid  = 1 + p;            // named barrier per pair

    float o[8][4];
#pragma unroll
    for (int g = 0; g < 8; ++g)
#pragma unroll
        for (int e = 0; e < 4; ++e) o[g][e] = 0.0f;
    float mr0 = -3.0e38f, mr1 = -3.0e38f, lr0 = 0.0f, lr1 = 0.0f;

    float* rmax = (float*)(smem + SM_RMAX);
    float* rsum = (float*)(smem + SM_RSUM);

    const int nkt = qt * 2 + 2;

    for (int kt = 0; kt < nkt; ++kt) {
        const int j0 = kt * 64;

        CP_WAIT0();
        __syncthreads();   // raw[kt] ready; all warps done reading bf16 K/V of kt-1
        convert_tile(smem, SM_RAWK, SM_KHI, SM_KLO, tid);
        convert_tile(smem, SM_RAWV, SM_VHI, SM_VLO, tid);
        __syncthreads();   // bf16 K/V ready; raw buffer free
        if (kt + 1 < nkt) prefetch_kv(sb, kptr, vptr, j0 + 64, tid);

        // ---- S (warp's j-half): s[4][4] ----
        float s[4][4];
#pragma unroll
        for (int g = 0; g < 4; ++g)
#pragma unroll
            for (int e = 0; e < 4; ++e) s[g][e] = 0.0f;

#pragma unroll
        for (int ck = 0; ck < 8; ++ck) {
            uint32_t ah[4], al[4];
            ldsm4(frag_addr(sb + SM_QHI, p << 4, ck << 4, l), ah);
            ldsm4(frag_addr(sb + SM_QLO, p << 4, ck << 4, l), al);
            uint32_t kh[2][4], kl[2][4];
#pragma unroll
            for (int g2 = 0; g2 < 2; ++g2) {
                const int jb = ((half << 1) + g2) << 4;
                ldsm4(frag_addr(sb + SM_KHI, jb, ck << 4, l), kh[g2]);
                ldsm4(frag_addr(sb + SM_KLO, jb, ck << 4, l), kl[g2]);
            }
#pragma unroll
            for (int g2 = 0; g2 < 2; ++g2) {
                mma16816(s[2 * g2],     ah, kh[g2][0], kh[g2][2]);
                mma16816(s[2 * g2 + 1], ah, kh[g2][1], kh[g2][3]);
            }
#pragma unroll
            for (int g2 = 0; g2 < 2; ++g2) {
                mma16816(s[2 * g2],     ah, kl[g2][0], kl[g2][2]);
                mma16816(s[2 * g2 + 1], ah, kl[g2][1], kl[g2][3]);
            }
#pragma unroll
            for (int g2 = 0; g2 < 2; ++g2) {
                mma16816(s[2 * g2],     al, kh[g2][0], kh[g2][2]);
                mma16816(s[2 * g2 + 1], al, kh[g2][1], kh[g2][3]);
            }
        }

        // ---- softmax (pair-scoped exchange) ----
        const int jb0 = j0 + (half << 5);
        const bool tm = (jb0 + 31 >= m0 + (p << 4));
        if (tm) {
#pragma unroll
            for (int g = 0; g < 4; ++g) {
                const int jg = jb0 + (g << 3) + qc;
                if (jg     >= ig0) s[g][0] = -1.0e10f;
                if (jg + 1 >= ig0) s[g][1] = -1.0e10f;
                if (jg     >= ig1) s[g][2] = -1.0e10f;
                if (jg + 1 >= ig1) s[g][3] = -1.0e10f;
            }
        }
        float mx0 = -3.0e38f, mx1 = -3.0e38f;
#pragma unroll
        for (int g = 0; g < 4; ++g) {
            mx0 = fmaxf(mx0, fmaxf(s[g][0], s[g][1]));
            mx1 = fmaxf(mx1, fmaxf(s[g][2], s[g][3]));
        }
        mx0 = fmaxf(mx0, __shfl_xor_sync(0xffffffffu, mx0, 1, 32));
        mx0 = fmaxf(mx0, __shfl_xor_sync(0xffffffffu, mx0, 2, 32));
        mx1 = fmaxf(mx1, __shfl_xor_sync(0xffffffffu, mx1, 1, 32));
        mx1 = fmaxf(mx1, __shfl_xor_sync(0xffffffffu, mx1, 2, 32));
        if ((l & 3) == 0) {
            rmax[(half << 7) + row0] = mx0;
            rmax[(half << 7) + row1] = mx1;
        }
        BARP(bid);

        const float rm0 = fmaxf(rmax[row0], rmax[128 + row0]);
        const float rm1 = fmaxf(rmax[row1], rmax[128 + row1]);
        const float mn0 = fmaxf(mr0, rm0), mn1 = fmaxf(mr1, rm1);
        const float a0  = exp2f((mr0 - mn0) * SCL);
        const float a1  = exp2f((mr1 - mn1) * SCL);

        float s0 = 0.0f, s1 = 0.0f;
#pragma unroll
        for (int g = 0; g < 4; ++g) {
#pragma unroll
            for (int e = 0; e < 2; ++e) {
                const int jg = jb0 + (g << 3) + qc + e;
                float p0 = (tm && jg >= ig0) ? 0.0f : exp2f((s[g][e] - mn0) * SCL);
                float p1 = (tm && jg >= ig1) ? 0.0f : exp2f((s[g][2 + e] - mn1) * SCL);
                s[g][e] = p0; s[g][2 + e] = p1;
                s0 += p0; s1 += p1;
            }
        }
        s0 += __shfl_xor_sync(0xffffffffu, s0, 1, 32);
        s0 += __shfl_xor_sync(0xffffffffu, s0, 2, 32);
        s1 += __shfl_xor_sync(0xffffffffu, s1, 1, 32);
        s1 += __shfl_xor_sync(0xffffffffu, s1, 2, 32);
        if ((l & 3) == 0) {
            rsum[(half << 7) + row0] = s0;
            rsum[(half << 7) + row1] = s1;
        }

        // ---- stage P hi/lo (warp's j-half), swizzled 128B rows ----
#pragma unroll
        for (int g = 0; g < 4; ++g) {
            const int colb = (((half << 5) + (g << 3) + qc)) << 1;
            uint32_t hw0 = pack_bf16(s[g][0], s[g][1]);
            uint32_t lw0 = pack_bf16(s[g][0] - bf_lo(hw0), s[g][1] - bf_hi(hw0));
            const int off0 = (row0 << 7) + (((colb >> 4) ^ (row0 & 7)) << 4) + (colb & 15);
            *(uint32_t*)(smem + SM_PHI + off0) = hw0;
            *(uint32_t*)(smem + SM_PLO + off0) = lw0;
            uint32_t hw1 = pack_bf16(s[g][2], s[g][3]);
            uint32_t lw1 = pack_bf16(s[g][2] - bf_lo(hw1), s[g][3] - bf_hi(hw1));
            const int off1 = (row1 << 7) + (((colb >> 4) ^ (row1 & 7)) << 4) + (colb & 15);
            *(uint32_t*)(smem + SM_PHI + off1) = hw1;
            *(uint32_t*)(smem + SM_PLO + off1) = lw1;
        }
        BARP(bid);         // P + rsum ready within pair

        const float t0 = rsum[row0] + rsum[128 + row0];
        const float t1 = rsum[row1] + rsum[128 + row1];
        lr0 = lr0 * a0 + t0; lr1 = lr1 * a1 + t1;
        mr0 = mn0; mr1 = mn1;
#pragma unroll
        for (int g = 0; g < 8; ++g) {
            o[g][0] *= a0; o[g][1] *= a0; o[g][2] *= a1; o[g][3] *= a1;
        }

        // ---- O += P V (full j, warp's c-half) ----
#pragma unroll
        for (int kk = 0; kk < 4; ++kk) {
            uint32_t pah[4], pal[4];
            ldsm4(frag_addr_p(sb + SM_PHI, p << 4, kk << 4, l), pah);
            ldsm4(frag_addr_p(sb + SM_PLO, p << 4, kk << 4, l), pal);
            uint32_t vh[4][4], vl[4][4];
#pragma unroll
            for (int i = 0; i < 4; ++i) {
                const int gp = (half << 2) + i;
                ldsm4t(frag_addr(sb + SM_VHI, kk << 4, gp << 4, l), vh[i]);
                ldsm4t(frag_addr(sb + SM_VLO, kk << 4, gp << 4, l), vl[i]);
            }
#pragma unroll
            for (int i = 0; i < 4; ++i) {
                mma16816(o[2 * i],     pah, vh[i][0], vh[i][1]);
                mma16816(o[2 * i + 1], pah, vh[i][2], vh[i][3]);
            }
#pragma unroll
            for (int i = 0; i < 4; ++i) {
                mma16816(o[2 * i],     pah, vl[i][0], vl[i][1]);
                mma16816(o[2 * i + 1], pah, vl[i][2], vl[i][3]);
            }
#pragma unroll
            for (int i = 0; i < 4; ++i) {
                mma16816(o[2 * i],     pal, vh[i][0], vh[i][1]);
                mma16816(o[2 * i + 1], pal, vh[i][2], vh[i][3]);
            }
        }
    }

    // ---- epilogue ----
    const float i0 = 1.0f / (lr0 + 1e-6f);
    const float i1 = 1.0f / (lr1 + 1e-6f);
    float* ob = out + bCN + m0 + (p << 4);
#pragma unroll
    for (int g = 0; g < 8; ++g) {
        const int c = (half << 6) + (g << 3) + qc;
        ob[(size_t)c * NSEQ + qr]           = o[g][0] * i0;
        ob[(size_t)(c + 1) * NSEQ + qr]     = o[g][1] * i0;
        ob[(size_t)c * NSEQ + qr + 8]       = o[g][2] * i1;
        ob[(size_t)(c + 1) * NSEQ + qr + 8] = o[g][3] * i1;
    }
}

extern "C" void kernel_launch(void* const* d_in, const int* in_sizes, int n_in,
                              void* d_out, int out_size)
{
    const float* key   = (const float*)d_in[0];
    const float* mixin = (const float*)d_in[1];
    const float* query = (const float*)d_in[2];
    float* out = (float*)d_out;

    cudaFuncSetAttribute(attn_hmma_kernel,
                         cudaFuncAttributeMaxDynamicSharedMemorySize, SMEM_BYTES);
    attn_hmma_kernel<<<256, NTHR, SMEM_BYTES>>>(key, mixin, query, out);
}

// round 8
// speedup vs baseline: 3.1543x; 1.0608x over previous
#include <cuda_runtime.h>
#include <cuda_bf16.h>
#include <cstdint>

// causal_attention: B=8, N=4096, d=128, fp32 [B,C,N] channel-major in/out.
// HMMA bf16 hi/lo-split flash attention.
// R8: two independent 256-thread CTAs per SM (64-row q-tiles,
// __launch_bounds__(256,2)) so one CTA's convert/softmax/barrier phases
// overlap the other's MMA phases. Per-warp work identical to R7.

constexpr int NSEQ = 4096;
constexpr int CDIM = 128;
constexpr int NTHR = 256;

// per-CTA SMEM byte offsets (64-row tiles)
constexpr int SM_QHI  = 0;          // 64 x 128 bf16 (16KB), 256B rows, swizzled
constexpr int SM_QLO  = 16384;
constexpr int SM_KHI  = 32768;      // 64 x 128 bf16 (16KB)
constexpr int SM_KLO  = 49152;
constexpr int SM_VHI  = 65536;
constexpr int SM_VLO  = 81920;
constexpr int SM_PHI  = 98304;      // 64 x 64 bf16 (8KB), 128B rows
constexpr int SM_PLO  = 106496;
constexpr int SM_RMAX = 114688;     // 2 x 64 floats
constexpr int SM_RSUM = 115200;
constexpr int SMEM_BYTES = 115712;  // x2 CTAs + 2x1KB reserved = 228KB/SM exactly

// 1/sqrt(128) * log2(e)
#define SCL 0.12751744955161f

__device__ __forceinline__ uint32_t su32(const void* p) {
    uint32_t a;
    asm("{ .reg .u64 t; cvta.to.shared.u64 t, %1; cvt.u32.u64 %0, t; }" : "=r"(a) : "l"(p));
    return a;
}
__device__ __forceinline__ uint32_t pack_bf16(float a, float b) {
    uint32_t r;
    asm("cvt.rn.bf16x2.f32 %0, %1, %2;" : "=r"(r) : "f"(b), "f"(a));
    return r;
}
__device__ __forceinline__ float bf_lo(uint32_t u) { return __uint_as_float(u << 16); }
__device__ __forceinline__ float bf_hi(uint32_t u) { return __uint_as_float(u & 0xffff0000u); }

__device__ __forceinline__ void ldsm4(uint32_t addr, uint32_t* r) {
    asm volatile("ldmatrix.sync.aligned.m8n8.x4.shared.b16 {%0,%1,%2,%3}, [%4];"
                 : "=r"(r[0]), "=r"(r[1]), "=r"(r[2]), "=r"(r[3]) : "r"(addr));
}
__device__ __forceinline__ void ldsm4t(uint32_t addr, uint32_t* r) {
    asm volatile("ldmatrix.sync.aligned.m8n8.x4.trans.shared.b16 {%0,%1,%2,%3}, [%4];"
                 : "=r"(r[0]), "=r"(r[1]), "=r"(r[2]), "=r"(r[3]) : "r"(addr));
}
__device__ __forceinline__ void mma16816(float* d, const uint32_t* a,
                                         uint32_t b0, uint32_t b1) {
    asm volatile(
        "mma.sync.aligned.m16n8k16.row.col.f32.bf16.bf16.f32 "
        "{%0,%1,%2,%3}, {%4,%5,%6,%7}, {%8,%9}, {%0,%1,%2,%3};"
        : "+f"(d[0]), "+f"(d[1]), "+f"(d[2]), "+f"(d[3])
        : "r"(a[0]), "r"(a[1]), "r"(a[2]), "r"(a[3]), "r"(b0), "r"(b1));
}
#define BARP(id) asm volatile("bar.sync %0, 64;" :: "r"(id) : "memory")

// ldmatrix.x4 lane address: 16x16 bf16 region, 256B row stride.
__device__ __forceinline__ uint32_t frag_addr(uint32_t base, int rb, int cb, int l) {
    int row = rb + (l & 7) + ((l >> 3) & 1) * 8;
    int col = cb + ((l >> 4) << 3);
    return base + (row << 8) + ((((col >> 3) ^ (row & 7)) << 4));
}
// P tile: 128B row stride.
__device__ __forceinline__ uint32_t frag_addr_p(uint32_t base, int rb, int cb, int l) {
    int row = rb + (l & 7) + ((l >> 3) & 1) * 8;
    int col = cb + ((l >> 4) << 3);
    return base + (row << 7) + ((((col >> 3) ^ (row & 7)) << 4));
}

// gmem fp32 [c][token] -> smem bf16 hi/lo [row=token][c], swizzled 256B rows,
// 64 rows x 128 channels.
__device__ __forceinline__ void fill_tile64(char* smem, int hi_off, int lo_off,
                                            const float* gsrc, int tok0, int tid) {
#pragma unroll
    for (int q4 = 0; q4 < 4; ++q4) {
        const int it = tid + q4 * NTHR;   // 0..1023
        const int r  = it & 63;
        const int c8 = (it >> 6) << 3;
        const float* g = gsrc + (size_t)c8 * NSEQ + tok0 + r;
        uint32_t hi[4], lo[4];
#pragma unroll
        for (int q = 0; q < 4; ++q) {
            float a = g[(size_t)(2 * q) * NSEQ];
            float c = g[(size_t)(2 * q + 1) * NSEQ];
            uint32_t h = pack_bf16(a, c);
            hi[q] = h;
            lo[q] = pack_bf16(a - bf_lo(h), c - bf_hi(h));
        }
        const int off = (r << 8) + ((((c8 >> 3) ^ (r & 7)) << 4));
        *(uint4*)(smem + hi_off + off) = make_uint4(hi[0], hi[1], hi[2], hi[3]);
        *(uint4*)(smem + lo_off + off) = make_uint4(lo[0], lo[1], lo[2], lo[3]);
    }
}

__global__ __launch_bounds__(NTHR, 2)
void attn_hmma_kernel(const float* __restrict__ key,
                      const float* __restrict__ mixin,
                      const float* __restrict__ query,
                      float* __restrict__ out)
{
    extern __shared__ char smem[];
    const uint32_t sb = su32(smem);

    const int tid  = threadIdx.x;
    const int l    = tid & 31;
    const int w    = tid >> 5;
    const int p    = w & 3;    // pair: q-rows 16p..16p+15 (of 64)
    const int half = w >> 2;   // 0: j 0-31 / c 0-63,  1: j 32-63 / c 64-127

    // 512 CTAs: 64 q-tiles x 8 batches, big tiles first
    const int bx = blockIdx.x;
    const int qt = 63 - (bx >> 3);
    const int b  = bx & 7;
    const int m0 = qt << 6;

    const size_t bCN = (size_t)b * CDIM * NSEQ;
    const float* kptr = key + bCN;
    const float* vptr = mixin + bCN;

    fill_tile64(smem, SM_QHI, SM_QLO, query + bCN, m0, tid);

    const int qr   = l >> 2;
    const int qc   = (l & 3) << 1;
    const int row0 = (p << 4) + qr;    // within 64-row tile
    const int row1 = row0 + 8;
    const int ig0  = m0 + row0;
    const int ig1  = m0 + row1;
    const int bid  = 1 + p;            // named barrier per pair

    float o[8][4];
#pragma unroll
    for (int g = 0; g < 8; ++g)
#pragma unroll
        for (int e = 0; e < 4; ++e) o[g][e] = 0.0f;
    float mr0 = -3.0e38f, mr1 = -3.0e38f, lr0 = 0.0f, lr1 = 0.0f;

    float* rmax = (float*)(smem + SM_RMAX);
    float* rsum = (float*)(smem + SM_RSUM);

    const int nkt = qt + 1;

    for (int kt = 0; kt < nkt; ++kt) {
        const int j0 = kt * 64;

        __syncthreads();   // all warps done reading K/V of kt-1 (and Q fill on kt=0)
        fill_tile64(smem, SM_KHI, SM_KLO, kptr, j0, tid);
        fill_tile64(smem, SM_VHI, SM_VLO, vptr, j0, tid);
        __syncthreads();   // bf16 K/V ready

        // ---- S (warp's j-half): s[4][4] ----
        float s[4][4];
#pragma unroll
        for (int g = 0; g < 4; ++g)
#pragma unroll
            for (int e = 0; e < 4; ++e) s[g][e] = 0.0f;

#pragma unroll
        for (int ck = 0; ck < 8; ++ck) {
            uint32_t ah[4], al[4];
            ldsm4(frag_addr(sb + SM_QHI, p << 4, ck << 4, l), ah);
            ldsm4(frag_addr(sb + SM_QLO, p << 4, ck << 4, l), al);
            uint32_t kh[2][4], kl[2][4];
#pragma unroll
            for (int g2 = 0; g2 < 2; ++g2) {
                const int jb = ((half << 1) + g2) << 4;
                ldsm4(frag_addr(sb + SM_KHI, jb, ck << 4, l), kh[g2]);
                ldsm4(frag_addr(sb + SM_KLO, jb, ck << 4, l), kl[g2]);
            }
#pragma unroll
            for (int g2 = 0; g2 < 2; ++g2) {
                mma16816(s[2 * g2],     ah, kh[g2][0], kh[g2][2]);
                mma16816(s[2 * g2 + 1], ah, kh[g2][1], kh[g2][3]);
            }
#pragma unroll
            for (int g2 = 0; g2 < 2; ++g2) {
                mma16816(s[2 * g2],     ah, kl[g2][0], kl[g2][2]);
                mma16816(s[2 * g2 + 1], ah, kl[g2][1], kl[g2][3]);
            }
#pragma unroll
            for (int g2 = 0; g2 < 2; ++g2) {
                mma16816(s[2 * g2],     al, kh[g2][0], kh[g2][2]);
                mma16816(s[2 * g2 + 1], al, kh[g2][1], kh[g2][3]);
            }
        }

        // ---- softmax (pair-scoped exchange) ----
        const int jb0 = j0 + (half << 5);
        const bool tm = (jb0 + 31 >= m0 + (p << 4));
        if (tm) {
#pragma unroll
            for (int g = 0; g < 4; ++g) {
                const int jg = jb0 + (g << 3) + qc;
                if (jg     >= ig0) s[g][0] = -1.0e10f;
                if (jg + 1 >= ig0) s[g][1] = -1.0e10f;
                if (jg     >= ig1) s[g][2] = -1.0e10f;
                if (jg + 1 >= ig1) s[g][3] = -1.0e10f;
            }
        }
        float mx0 = -3.0e38f, mx1 = -3.0e38f;
#pragma unroll
        for (int g = 0; g < 4; ++g) {
            mx0 = fmaxf(mx0, fmaxf(s[g][0], s[g][1]));
            mx1 = fmaxf(mx1, fmaxf(s[g][2], s[g][3]));
        }
        mx0 = fmaxf(mx0, __shfl_xor_sync(0xffffffffu, mx0, 1, 32));
        mx0 = fmaxf(mx0, __shfl_xor_sync(0xffffffffu, mx0, 2, 32));
        mx1 = fmaxf(mx1, __shfl_xor_sync(0xffffffffu, mx1, 1, 32));
        mx1 = fmaxf(mx1, __shfl_xor_sync(0xffffffffu, mx1, 2, 32));
        if ((l & 3) == 0) {
            rmax[(half << 6) + row0] = mx0;
            rmax[(half << 6) + row1] = mx1;
        }
        BARP(bid);

        const float rm0 = fmaxf(rmax[row0], rmax[64 + row0]);
        const float rm1 = fmaxf(rmax[row1], rmax[64 + row1]);
        const float mn0 = fmaxf(mr0, rm0), mn1 = fmaxf(mr1, rm1);
        const float a0  = exp2f((mr0 - mn0) * SCL);
        const float a1  = exp2f((mr1 - mn1) * SCL);

        float s0 = 0.0f, s1 = 0.0f;
#pragma unroll
        for (int g = 0; g < 4; ++g) {
#pragma unroll
            for (int e = 0; e < 2; ++e) {
                const int jg = jb0 + (g << 3) + qc + e;
                float p0 = (tm && jg >= ig0) ? 0.0f : exp2f((s[g][e] - mn0) * SCL);
                float p1 = (tm && jg >= ig1) ? 0.0f : exp2f((s[g][2 + e] - mn1) * SCL);
                s[g][e] = p0; s[g][2 + e] = p1;
                s0 += p0; s1 += p1;
            }
        }
        s0 += __shfl_xor_sync(0xffffffffu, s0, 1, 32);
        s0 += __shfl_xor_sync(0xffffffffu, s0, 2, 32);
        s1 += __shfl_xor_sync(0xffffffffu, s1, 1, 32);
        s1 += __shfl_xor_sync(0xffffffffu, s1, 2, 32);
        if ((l & 3) == 0) {
            rsum[(half << 6) + row0] = s0;
            rsum[(half << 6) + row1] = s1;
        }

        // ---- stage P hi/lo (warp's j-half), swizzled 128B rows ----
#pragma unroll
        for (int g = 0; g < 4; ++g) {
            const int colb = (((half << 5) + (g << 3) + qc)) << 1;
            uint32_t hw0 = pack_bf16(s[g][0], s[g][1]);
            uint32_t lw0 = pack_bf16(s[g][0] - bf_lo(hw0), s[g][1] - bf_hi(hw0));
            const int off0 = (row0 << 7) + (((colb >> 4) ^ (row0 & 7)) << 4) + (colb & 15);
            *(uint32_t*)(smem + SM_PHI + off0) = hw0;
            *(uint32_t*)(smem + SM_PLO + off0) = lw0;
            uint32_t hw1 = pack_bf16(s[g][2], s[g][3]);
            uint32_t lw1 = pack_bf16(s[g][2] - bf_lo(hw1), s[g][3] - bf_hi(hw1));
            const int off1 = (row1 << 7) + (((colb >> 4) ^ (row1 & 7)) << 4) + (colb & 15);
            *(uint32_t*)(smem + SM_PHI + off1) = hw1;
            *(uint32_t*)(smem + SM_PLO + off1) = lw1;
        }
        BARP(bid);         // P + rsum ready within pair

        const float t0 = rsum[row0] + rsum[64 + row0];
        const float t1 = rsum[row1] + rsum[64 + row1];
        lr0 = lr0 * a0 + t0; lr1 = lr1 * a1 + t1;
        mr0 = mn0; mr1 = mn1;
#pragma unroll
        for (int g = 0; g < 8; ++g) {
            o[g][0] *= a0; o[g][1] *= a0; o[g][2] *= a1; o[g][3] *= a1;
        }

        // ---- O += P V (full j, warp's c-half) ----
#pragma unroll
        for (int kk = 0; kk < 4; ++kk) {
            uint32_t pah[4], pal[4];
            ldsm4(frag_addr_p(sb + SM_PHI, p << 4, kk << 4, l), pah);
            ldsm4(frag_addr_p(sb + SM_PLO, p << 4, kk << 4, l), pal);
            uint32_t vh[4][4], vl[4][4];
#pragma unroll
            for (int i = 0; i < 4; ++i) {
                const int gp = (half << 2) + i;
                ldsm4t(frag_addr(sb + SM_VHI, kk << 4, gp << 4, l), vh[i]);
                ldsm4t(frag_addr(sb + SM_VLO, kk << 4, gp << 4, l), vl[i]);
            }
#pragma unroll
            for (int i = 0; i < 4; ++i) {
                mma16816(o[2 * i],     pah, vh[i][0], vh[i][1]);
                mma16816(o[2 * i + 1], pah, vh[i][2], vh[i][3]);
            }
#pragma unroll
            for (int i = 0; i < 4; ++i) {
                mma16816(o[2 * i],     pah, vl[i][0], vl[i][1]);
                mma16816(o[2 * i + 1], pah, vl[i][2], vl[i][3]);
            }
#pragma unroll
            for (int i = 0; i < 4; ++i) {
                mma16816(o[2 * i],     pal, vh[i][0], vh[i][1]);
                mma16816(o[2 * i + 1], pal, vh[i][2], vh[i][3]);
            }
        }
    }

    // ---- epilogue ----
    const float i0 = 1.0f / (lr0 + 1e-6f);
    const float i1 = 1.0f / (lr1 + 1e-6f);
    float* ob = out + bCN + m0 + (p << 4);
#pragma unroll
    for (int g = 0; g < 8; ++g) {
        const int c = (half << 6) + (g << 3) + qc;
        ob[(size_t)c * NSEQ + qr]           = o[g][0] * i0;
        ob[(size_t)(c + 1) * NSEQ + qr]     = o[g][1] * i0;
        ob[(size_t)c * NSEQ + qr + 8]       = o[g][2] * i1;
        ob[(size_t)(c + 1) * NSEQ + qr + 8] = o[g][3] * i1;
    }
}

extern "C" void kernel_launch(void* const* d_in, const int* in_sizes, int n_in,
                              void* d_out, int out_size)
{
    const float* key   = (const float*)d_in[0];
    const float* mixin = (const float*)d_in[1];
    const float* query = (const float*)d_in[2];
    float* out = (float*)d_out;

    cudaFuncSetAttribute(attn_hmma_kernel,
                         cudaFuncAttributeMaxDynamicSharedMemorySize, SMEM_BYTES);
    attn_hmma_kernel<<<512, NTHR, SMEM_BYTES>>>(key, mixin, query, out);
}

// round 9
// speedup vs baseline: 4.3654x; 1.3840x over previous
#include <cuda_runtime.h>
#include <cuda_fp16.h>
#include <cstdint>

// causal_attention: B=8, N=4096, d=128, fp32 [B,C,N] channel-major in/out.
// HMMA fp16 flash attention. R9: 2-term fp16 split (Qh+Ql)*K, (Ph+Pl)*V —
// unsplit operand single fp16 (2^-11 rel error). 33% fewer MMAs, 50% less
// K/V smem traffic than 3-term bf16. 2 CTAs/SM, 64-row q-tiles.

constexpr int NSEQ = 4096;
constexpr int CDIM = 128;
constexpr int NTHR = 256;

// per-CTA SMEM byte offsets
constexpr int SM_QHI  = 0;          // 64 x 128 f16 (16KB), 256B rows, swizzled
constexpr int SM_QLO  = 16384;
constexpr int SM_K    = 32768;      // 64 x 128 f16 (16KB), single plane
constexpr int SM_V    = 49152;
constexpr int SM_PHI  = 65536;      // 64 x 64 f16 (8KB), 128B rows
constexpr int SM_PLO  = 73728;
constexpr int SM_RMAX = 81920;      // 2 x 64 floats
constexpr int SM_RSUM = 82432;
constexpr int SMEM_BYTES = 82944;   // x2 CTAs = 162KB/SM

// 1/sqrt(128) * log2(e)
#define SCL 0.12751744955161f

__device__ __forceinline__ uint32_t su32(const void* p) {
    uint32_t a;
    asm("{ .reg .u64 t; cvta.to.shared.u64 t, %1; cvt.u32.u64 %0, t; }" : "=r"(a) : "l"(p));
    return a;
}
// pack two f32 -> f16x2 (lo = a, hi = b)
__device__ __forceinline__ uint32_t pack_f16(float a, float b) {
    uint32_t r;
    asm("cvt.rn.f16x2.f32 %0, %1, %2;" : "=r"(r) : "f"(b), "f"(a));
    return r;
}
__device__ __forceinline__ float f16_lo(uint32_t u) {
    float f;
    asm("{ .reg .b16 h, hh; mov.b32 {h, hh}, %1; cvt.f32.f16 %0, h; }" : "=f"(f) : "r"(u));
    return f;
}
__device__ __forceinline__ float f16_hi(uint32_t u) {
    float f;
    asm("{ .reg .b16 h, hh; mov.b32 {h, hh}, %1; cvt.f32.f16 %0, hh; }" : "=f"(f) : "r"(u));
    return f;
}

__device__ __forceinline__ void ldsm4(uint32_t addr, uint32_t* r) {
    asm volatile("ldmatrix.sync.aligned.m8n8.x4.shared.b16 {%0,%1,%2,%3}, [%4];"
                 : "=r"(r[0]), "=r"(r[1]), "=r"(r[2]), "=r"(r[3]) : "r"(addr));
}
__device__ __forceinline__ void ldsm4t(uint32_t addr, uint32_t* r) {
    asm volatile("ldmatrix.sync.aligned.m8n8.x4.trans.shared.b16 {%0,%1,%2,%3}, [%4];"
                 : "=r"(r[0]), "=r"(r[1]), "=r"(r[2]), "=r"(r[3]) : "r"(addr));
}
__device__ __forceinline__ void mma16816(float* d, const uint32_t* a,
                                         uint32_t b0, uint32_t b1) {
    asm volatile(
        "mma.sync.aligned.m16n8k16.row.col.f32.f16.f16.f32 "
        "{%0,%1,%2,%3}, {%4,%5,%6,%7}, {%8,%9}, {%0,%1,%2,%3};"
        : "+f"(d[0]), "+f"(d[1]), "+f"(d[2]), "+f"(d[3])
        : "r"(a[0]), "r"(a[1]), "r"(a[2]), "r"(a[3]), "r"(b0), "r"(b1));
}
#define BARP(id) asm volatile("bar.sync %0, 64;" :: "r"(id) : "memory")

// ldmatrix.x4 lane address: 16x16 f16 region, 256B row stride.
__device__ __forceinline__ uint32_t frag_addr(uint32_t base, int rb, int cb, int l) {
    int row = rb + (l & 7) + ((l >> 3) & 1) * 8;
    int col = cb + ((l >> 4) << 3);
    return base + (row << 8) + ((((col >> 3) ^ (row & 7)) << 4));
}
// P tile: 128B row stride.
__device__ __forceinline__ uint32_t frag_addr_p(uint32_t base, int rb, int cb, int l) {
    int row = rb + (l & 7) + ((l >> 3) & 1) * 8;
    int col = cb + ((l >> 4) << 3);
    return base + (row << 7) + ((((col >> 3) ^ (row & 7)) << 4));
}

// gmem fp32 [c][token] -> smem f16 single plane [row=token][c], 64 rows.
__device__ __forceinline__ void fill_f16(char* smem, int off,
                                         const float* gsrc, int tok0, int tid) {
#pragma unroll
    for (int q4 = 0; q4 < 4; ++q4) {
        const int it = tid + q4 * NTHR;
        const int r  = it & 63;
        const int c8 = (it >> 6) << 3;
        const float* g = gsrc + (size_t)c8 * NSEQ + tok0 + r;
        uint32_t h[4];
#pragma unroll
        for (int q = 0; q < 4; ++q)
            h[q] = pack_f16(g[(size_t)(2 * q) * NSEQ], g[(size_t)(2 * q + 1) * NSEQ]);
        const int o = (r << 8) + ((((c8 >> 3) ^ (r & 7)) << 4));
        *(uint4*)(smem + off + o) = make_uint4(h[0], h[1], h[2], h[3]);
    }
}
// same, hi/lo split planes (for Q).
__device__ __forceinline__ void fill_f16_hl(char* smem, int hi_off, int lo_off,
                                            const float* gsrc, int tok0, int tid) {
#pragma unroll
    for (int q4 = 0; q4 < 4; ++q4) {
        const int it = tid + q4 * NTHR;
        const int r  = it & 63;
        const int c8 = (it >> 6) << 3;
        const float* g = gsrc + (size_t)c8 * NSEQ + tok0 + r;
        uint32_t hi[4], lo[4];
#pragma unroll
        for (int q = 0; q < 4; ++q) {
            float a = g[(size_t)(2 * q) * NSEQ];
            float c = g[(size_t)(2 * q + 1) * NSEQ];
            uint32_t h = pack_f16(a, c);
            hi[q] = h;
            lo[q] = pack_f16(a - f16_lo(h), c - f16_hi(h));
        }
        const int o = (r << 8) + ((((c8 >> 3) ^ (r & 7)) << 4));
        *(uint4*)(smem + hi_off + o) = make_uint4(hi[0], hi[1], hi[2], hi[3]);
        *(uint4*)(smem + lo_off + o) = make_uint4(lo[0], lo[1], lo[2], lo[3]);
    }
}

__global__ __launch_bounds__(NTHR, 2)
void attn_hmma_kernel(const float* __restrict__ key,
                      const float* __restrict__ mixin,
                      const float* __restrict__ query,
                      float* __restrict__ out)
{
    extern __shared__ char smem[];
    const uint32_t sb = su32(smem);

    const int tid  = threadIdx.x;
    const int l    = tid & 31;
    const int w    = tid >> 5;
    const int p    = w & 3;    // pair: q-rows 16p..16p+15 (of 64)
    const int half = w >> 2;   // 0: j 0-31 / c 0-63,  1: j 32-63 / c 64-127

    const int bx = blockIdx.x;
    const int qt = 63 - (bx >> 3);
    const int b  = bx & 7;
    const int m0 = qt << 6;

    const size_t bCN = (size_t)b * CDIM * NSEQ;
    const float* kptr = key + bCN;
    const float* vptr = mixin + bCN;

    fill_f16_hl(smem, SM_QHI, SM_QLO, query + bCN, m0, tid);

    const int qr   = l >> 2;
    const int qc   = (l & 3) << 1;
    const int row0 = (p << 4) + qr;
    const int row1 = row0 + 8;
    const int ig0  = m0 + row0;
    const int ig1  = m0 + row1;
    const int bid  = 1 + p;

    float o[8][4];
#pragma unroll
    for (int g = 0; g < 8; ++g)
#pragma unroll
        for (int e = 0; e < 4; ++e) o[g][e] = 0.0f;
    float mr0 = -3.0e38f, mr1 = -3.0e38f, lr0 = 0.0f, lr1 = 0.0f;

    float* rmax = (float*)(smem + SM_RMAX);
    float* rsum = (float*)(smem + SM_RSUM);

    const int nkt = qt + 1;

    for (int kt = 0; kt < nkt; ++kt) {
        const int j0 = kt * 64;

        __syncthreads();   // all warps done reading K/V of kt-1 (and Q fill on kt=0)
        fill_f16(smem, SM_K, kptr, j0, tid);
        fill_f16(smem, SM_V, vptr, j0, tid);
        __syncthreads();

        // ---- S (warp's j-half) = (Qh + Ql) * K ----
        float s[4][4];
#pragma unroll
        for (int g = 0; g < 4; ++g)
#pragma unroll
            for (int e = 0; e < 4; ++e) s[g][e] = 0.0f;

#pragma unroll
        for (int ck = 0; ck < 8; ++ck) {
            uint32_t ah[4], al[4];
            ldsm4(frag_addr(sb + SM_QHI, p << 4, ck << 4, l), ah);
            ldsm4(frag_addr(sb + SM_QLO, p << 4, ck << 4, l), al);
            uint32_t kf[2][4];
#pragma unroll
            for (int g2 = 0; g2 < 2; ++g2) {
                const int jb = ((half << 1) + g2) << 4;
                ldsm4(frag_addr(sb + SM_K, jb, ck << 4, l), kf[g2]);
            }
#pragma unroll
            for (int g2 = 0; g2 < 2; ++g2) {
                mma16816(s[2 * g2],     ah, kf[g2][0], kf[g2][2]);
                mma16816(s[2 * g2 + 1], ah, kf[g2][1], kf[g2][3]);
            }
#pragma unroll
            for (int g2 = 0; g2 < 2; ++g2) {
                mma16816(s[2 * g2],     al, kf[g2][0], kf[g2][2]);
                mma16816(s[2 * g2 + 1], al, kf[g2][1], kf[g2][3]);
            }
        }

        // ---- softmax (pair-scoped exchange) ----
        const int jb0 = j0 + (half << 5);
        const bool tm = (jb0 + 31 >= m0 + (p << 4));
        if (tm) {
#pragma unroll
            for (int g = 0; g < 4; ++g) {
                const int jg = jb0 + (g << 3) + qc;
                if (jg     >= ig0) s[g][0] = -1.0e10f;
                if (jg + 1 >= ig0) s[g][1] = -1.0e10f;
                if (jg     >= ig1) s[g][2] = -1.0e10f;
                if (jg + 1 >= ig1) s[g][3] = -1.0e10f;
            }
        }
        float mx0 = -3.0e38f, mx1 = -3.0e38f;
#pragma unroll
        for (int g = 0; g < 4; ++g) {
            mx0 = fmaxf(mx0, fmaxf(s[g][0], s[g][1]));
            mx1 = fmaxf(mx1, fmaxf(s[g][2], s[g][3]));
        }
        mx0 = fmaxf(mx0, __shfl_xor_sync(0xffffffffu, mx0, 1, 32));
        mx0 = fmaxf(mx0, __shfl_xor_sync(0xffffffffu, mx0, 2, 32));
        mx1 = fmaxf(mx1, __shfl_xor_sync(0xffffffffu, mx1, 1, 32));
        mx1 = fmaxf(mx1, __shfl_xor_sync(0xffffffffu, mx1, 2, 32));
        if ((l & 3) == 0) {
            rmax[(half << 6) + row0] = mx0;
            rmax[(half << 6) + row1] = mx1;
        }
        BARP(bid);

        const float rm0 = fmaxf(rmax[row0], rmax[64 + row0]);
        const float rm1 = fmaxf(rmax[row1], rmax[64 + row1]);
        const float mn0 = fmaxf(mr0, rm0), mn1 = fmaxf(mr1, rm1);
        const float a0  = exp2f((mr0 - mn0) * SCL);
        const float a1  = exp2f((mr1 - mn1) * SCL);

        float s0 = 0.0f, s1 = 0.0f;
#pragma unroll
        for (int g = 0; g < 4; ++g) {
#pragma unroll
            for (int e = 0; e < 2; ++e) {
                const int jg = jb0 + (g << 3) + qc + e;
                float p0 = (tm && jg >= ig0) ? 0.0f : exp2f((s[g][e] - mn0) * SCL);
                float p1 = (tm && jg >= ig1) ? 0.0f : exp2f((s[g][2 + e] - mn1) * SCL);
                s[g][e] = p0; s[g][2 + e] = p1;
                s0 += p0; s1 += p1;
            }
        }
        s0 += __shfl_xor_sync(0xffffffffu, s0, 1, 32);
        s0 += __shfl_xor_sync(0xffffffffu, s0, 2, 32);
        s1 += __shfl_xor_sync(0xffffffffu, s1, 1, 32);
        s1 += __shfl_xor_sync(0xffffffffu, s1, 2, 32);
        if ((l & 3) == 0) {
            rsum[(half << 6) + row0] = s0;
            rsum[(half << 6) + row1] = s1;
        }

        // ---- stage P hi/lo (warp's j-half), swizzled 128B rows ----
#pragma unroll
        for (int g = 0; g < 4; ++g) {
            const int colb = (((half << 5) + (g << 3) + qc)) << 1;
            uint32_t hw0 = pack_f16(s[g][0], s[g][1]);
            uint32_t lw0 = pack_f16(s[g][0] - f16_lo(hw0), s[g][1] - f16_hi(hw0));
            const int off0 = (row0 << 7) + (((colb >> 4) ^ (row0 & 7)) << 4) + (colb & 15);
            *(uint32_t*)(smem + SM_PHI + off0) = hw0;
            *(uint32_t*)(smem + SM_PLO + off0) = lw0;
            uint32_t hw1 = pack_f16(s[g][2], s[g][3]);
            uint32_t lw1 = pack_f16(s[g][2] - f16_lo(hw1), s[g][3] - f16_hi(hw1));
            const int off1 = (row1 << 7) + (((colb >> 4) ^ (row1 & 7)) << 4) + (colb & 15);
            *(uint32_t*)(smem + SM_PHI + off1) = hw1;
            *(uint32_t*)(smem + SM_PLO + off1) = lw1;
        }
        BARP(bid);

        const float t0 = rsum[row0] + rsum[64 + row0];
        const float t1 = rsum[row1] + rsum[64 + row1];
        lr0 = lr0 * a0 + t0; lr1 = lr1 * a1 + t1;
        mr0 = mn0; mr1 = mn1;
#pragma unroll
        for (int g = 0; g < 8; ++g) {
            o[g][0] *= a0; o[g][1] *= a0; o[g][2] *= a1; o[g][3] *= a1;
        }

        // ---- O += (Ph + Pl) * V (full j, warp's c-half) ----
#pragma unroll
        for (int kk = 0; kk < 4; ++kk) {
            uint32_t pah[4], pal[4];
            ldsm4(frag_addr_p(sb + SM_PHI, p << 4, kk << 4, l), pah);
            ldsm4(frag_addr_p(sb + SM_PLO, p << 4, kk << 4, l), pal);
            uint32_t vf[4][4];
#pragma unroll
            for (int i = 0; i < 4; ++i) {
                const int gp = (half << 2) + i;
                ldsm4t(frag_addr(sb + SM_V, kk << 4, gp << 4, l), vf[i]);
            }
#pragma unroll
            for (int i = 0; i < 4; ++i) {
                mma16816(o[2 * i],     pah, vf[i][0], vf[i][1]);
                mma16816(o[2 * i + 1], pah, vf[i][2], vf[i][3]);
            }
#pragma unroll
            for (int i = 0; i < 4; ++i) {
                mma16816(o[2 * i],     pal, vf[i][0], vf[i][1]);
                mma16816(o[2 * i + 1], pal, vf[i][2], vf[i][3]);
            }
        }
    }

    // ---- epilogue ----
    const float i0 = 1.0f / (lr0 + 1e-6f);
    const float i1 = 1.0f / (lr1 + 1e-6f);
    float* ob = out + bCN + m0 + (p << 4);
#pragma unroll
    for (int g = 0; g < 8; ++g) {
        const int c = (half << 6) + (g << 3) + qc;
        ob[(size_t)c * NSEQ + qr]           = o[g][0] * i0;
        ob[(size_t)(c + 1) * NSEQ + qr]     = o[g][1] * i0;
        ob[(size_t)c * NSEQ + qr + 8]       = o[g][2] * i1;
        ob[(size_t)(c + 1) * NSEQ + qr + 8] = o[g][3] * i1;
    }
}

extern "C" void kernel_launch(void* const* d_in, const int* in_sizes, int n_in,
                              void* d_out, int out_size)
{
    const float* key   = (const float*)d_in[0];
    const float* mixin = (const float*)d_in[1];
    const float* query = (const float*)d_in[2];
    float* out = (float*)d_out;

    cudaFuncSetAttribute(attn_hmma_kernel,
                         cudaFuncAttributeMaxDynamicSharedMemorySize, SMEM_BYTES);
    attn_hmma_kernel<<<512, NTHR, SMEM_BYTES>>>(key, mixin, query, out);
}

// round 11
// speedup vs baseline: 4.8590x; 1.1131x over previous
#include <cuda_runtime.h>
#include <cuda_fp16.h>
#include <cstdint>

// causal_attention: B=8, N=4096, d=128, fp32 [B,C,N] channel-major in/out.
// HMMA fp16 flash attention. R11: S = (Qh+Ql)*K (2-term); O += P*V with
// single-f16 P; p computed in f32 (exp2f), packed to f16x2; denominator
// sums the f16-rounded p (consistent with numerator). 2 CTAs/SM.

constexpr int NSEQ = 4096;
constexpr int CDIM = 128;
constexpr int NTHR = 256;

// per-CTA SMEM byte offsets
constexpr int SM_QHI  = 0;          // 64 x 128 f16 (16KB), 256B rows, swizzled
constexpr int SM_QLO  = 16384;
constexpr int SM_K    = 32768;      // 64 x 128 f16 (16KB), single plane
constexpr int SM_V    = 49152;
constexpr int SM_P    = 65536;      // 64 x 64 f16 (8KB), 128B rows
constexpr int SM_RMAX = 73728;      // 2 x 64 floats
constexpr int SM_RSUM = 74240;
constexpr int SMEM_BYTES = 74752;   // x2 CTAs = 146KB/SM

// 1/sqrt(128) * log2(e)
#define SCL 0.12751744955161f

__device__ __forceinline__ uint32_t su32(const void* p) {
    uint32_t a;
    asm("{ .reg .u64 t; cvta.to.shared.u64 t, %1; cvt.u32.u64 %0, t; }" : "=r"(a) : "l"(p));
    return a;
}
// pack two f32 -> f16x2 (lo = a, hi = b)
__device__ __forceinline__ uint32_t pack_f16(float a, float b) {
    uint32_t r;
    asm("cvt.rn.f16x2.f32 %0, %1, %2;" : "=r"(r) : "f"(b), "f"(a));
    return r;
}
__device__ __forceinline__ float f16_lo(uint32_t u) {
    float f;
    asm("{ .reg .b16 h, hh; mov.b32 {h, hh}, %1; cvt.f32.f16 %0, h; }" : "=f"(f) : "r"(u));
    return f;
}
__device__ __forceinline__ float f16_hi(uint32_t u) {
    float f;
    asm("{ .reg .b16 h, hh; mov.b32 {h, hh}, %1; cvt.f32.f16 %0, hh; }" : "=f"(f) : "r"(u));
    return f;
}

__device__ __forceinline__ void ldsm4(uint32_t addr, uint32_t* r) {
    asm volatile("ldmatrix.sync.aligned.m8n8.x4.shared.b16 {%0,%1,%2,%3}, [%4];"
                 : "=r"(r[0]), "=r"(r[1]), "=r"(r[2]), "=r"(r[3]) : "r"(addr));
}
__device__ __forceinline__ void ldsm4t(uint32_t addr, uint32_t* r) {
    asm volatile("ldmatrix.sync.aligned.m8n8.x4.trans.shared.b16 {%0,%1,%2,%3}, [%4];"
                 : "=r"(r[0]), "=r"(r[1]), "=r"(r[2]), "=r"(r[3]) : "r"(addr));
}
__device__ __forceinline__ void mma16816(float* d, const uint32_t* a,
                                         uint32_t b0, uint32_t b1) {
    asm volatile(
        "mma.sync.aligned.m16n8k16.row.col.f32.f16.f16.f32 "
        "{%0,%1,%2,%3}, {%4,%5,%6,%7}, {%8,%9}, {%0,%1,%2,%3};"
        : "+f"(d[0]), "+f"(d[1]), "+f"(d[2]), "+f"(d[3])
        : "r"(a[0]), "r"(a[1]), "r"(a[2]), "r"(a[3]), "r"(b0), "r"(b1));
}
#define BARP(id) asm volatile("bar.sync %0, 64;" :: "r"(id) : "memory")

// ldmatrix.x4 lane address: 16x16 f16 region, 256B row stride.
__device__ __forceinline__ uint32_t frag_addr(uint32_t base, int rb, int cb, int l) {
    int row = rb + (l & 7) + ((l >> 3) & 1) * 8;
    int col = cb + ((l >> 4) << 3);
    return base + (row << 8) + ((((col >> 3) ^ (row & 7)) << 4));
}
// P tile: 128B row stride.
__device__ __forceinline__ uint32_t frag_addr_p(uint32_t base, int rb, int cb, int l) {
    int row = rb + (l & 7) + ((l >> 3) & 1) * 8;
    int col = cb + ((l >> 4) << 3);
    return base + (row << 7) + ((((col >> 3) ^ (row & 7)) << 4));
}

// gmem fp32 [c][token] -> smem f16 single plane [row=token][c], 64 rows.
__device__ __forceinline__ void fill_f16(char* smem, int off,
                                         const float* gsrc, int tok0, int tid) {
#pragma unroll
    for (int q4 = 0; q4 < 4; ++q4) {
        const int it = tid + q4 * NTHR;
        const int r  = it & 63;
        const int c8 = (it >> 6) << 3;
        const float* g = gsrc + (size_t)c8 * NSEQ + tok0 + r;
        uint32_t h[4];
#pragma unroll
        for (int q = 0; q < 4; ++q)
            h[q] = pack_f16(g[(size_t)(2 * q) * NSEQ], g[(size_t)(2 * q + 1) * NSEQ]);
        const int o = (r << 8) + ((((c8 >> 3) ^ (r & 7)) << 4));
        *(uint4*)(smem + off + o) = make_uint4(h[0], h[1], h[2], h[3]);
    }
}
// same, hi/lo split planes (for Q).
__device__ __forceinline__ void fill_f16_hl(char* smem, int hi_off, int lo_off,
                                            const float* gsrc, int tok0, int tid) {
#pragma unroll
    for (int q4 = 0; q4 < 4; ++q4) {
        const int it = tid + q4 * NTHR;
        const int r  = it & 63;
        const int c8 = (it >> 6) << 3;
        const float* g = gsrc + (size_t)c8 * NSEQ + tok0 + r;
        uint32_t hi[4], lo[4];
#pragma unroll
        for (int q = 0; q < 4; ++q) {
            float a = g[(size_t)(2 * q) * NSEQ];
            float c = g[(size_t)(2 * q + 1) * NSEQ];
            uint32_t h = pack_f16(a, c);
            hi[q] = h;
            lo[q] = pack_f16(a - f16_lo(h), c - f16_hi(h));
        }
        const int o = (r << 8) + ((((c8 >> 3) ^ (r & 7)) << 4));
        *(uint4*)(smem + hi_off + o) = make_uint4(hi[0], hi[1], hi[2], hi[3]);
        *(uint4*)(smem + lo_off + o) = make_uint4(lo[0], lo[1], lo[2], lo[3]);
    }
}

__global__ __launch_bounds__(NTHR, 2)
void attn_hmma_kernel(const float* __restrict__ key,
                      const float* __restrict__ mixin,
                      const float* __restrict__ query,
                      float* __restrict__ out)
{
    extern __shared__ char smem[];
    const uint32_t sb = su32(smem);

    const int tid  = threadIdx.x;
    const int l    = tid & 31;
    const int w    = tid >> 5;
    const int p    = w & 3;    // pair: q-rows 16p..16p+15 (of 64)
    const int half = w >> 2;   // 0: j 0-31 / c 0-63,  1: j 32-63 / c 64-127

    const int bx = blockIdx.x;
    const int qt = 63 - (bx >> 3);
    const int b  = bx & 7;
    const int m0 = qt << 6;

    const size_t bCN = (size_t)b * CDIM * NSEQ;
    const float* kptr = key + bCN;
    const float* vptr = mixin + bCN;

    fill_f16_hl(smem, SM_QHI, SM_QLO, query + bCN, m0, tid);

    const int qr   = l >> 2;
    const int qc   = (l & 3) << 1;
    const int row0 = (p << 4) + qr;
    const int row1 = row0 + 8;
    const int ig0  = m0 + row0;
    const int ig1  = m0 + row1;
    const int bid  = 1 + p;

    float o[8][4];
#pragma unroll
    for (int g = 0; g < 8; ++g)
#pragma unroll
        for (int e = 0; e < 4; ++e) o[g][e] = 0.0f;
    float mr0 = -3.0e38f, mr1 = -3.0e38f, lr0 = 0.0f, lr1 = 0.0f;

    float* rmax = (float*)(smem + SM_RMAX);
    float* rsum = (float*)(smem + SM_RSUM);

    const int nkt = qt + 1;

    for (int kt = 0; kt < nkt; ++kt) {
        const int j0 = kt * 64;

        __syncthreads();   // all warps done reading K/V of kt-1 (and Q fill on kt=0)
        fill_f16(smem, SM_K, kptr, j0, tid);
        fill_f16(smem, SM_V, vptr, j0, tid);
        __syncthreads();

        // ---- S (warp's j-half) = (Qh + Ql) * K ----
        float s[4][4];
#pragma unroll
        for (int g = 0; g < 4; ++g)
#pragma unroll
            for (int e = 0; e < 4; ++e) s[g][e] = 0.0f;

#pragma unroll
        for (int ck = 0; ck < 8; ++ck) {
            uint32_t ah[4], al[4];
            ldsm4(frag_addr(sb + SM_QHI, p << 4, ck << 4, l), ah);
            ldsm4(frag_addr(sb + SM_QLO, p << 4, ck << 4, l), al);
            uint32_t kf[2][4];
#pragma unroll
            for (int g2 = 0; g2 < 2; ++g2) {
                const int jb = ((half << 1) + g2) << 4;
                ldsm4(frag_addr(sb + SM_K, jb, ck << 4, l), kf[g2]);
            }
#pragma unroll
            for (int g2 = 0; g2 < 2; ++g2) {
                mma16816(s[2 * g2],     ah, kf[g2][0], kf[g2][2]);
                mma16816(s[2 * g2 + 1], ah, kf[g2][1], kf[g2][3]);
            }
#pragma unroll
            for (int g2 = 0; g2 < 2; ++g2) {
                mma16816(s[2 * g2],     al, kf[g2][0], kf[g2][2]);
                mma16816(s[2 * g2 + 1], al, kf[g2][1], kf[g2][3]);
            }
        }

        // ---- softmax (pair-scoped exchange) ----
        const int jb0 = j0 + (half << 5);
        const bool tm = (jb0 + 31 >= m0 + (p << 4));
        if (tm) {
#pragma unroll
            for (int g = 0; g < 4; ++g) {
                const int jg = jb0 + (g << 3) + qc;
                if (jg     >= ig0) s[g][0] = -1.0e10f;
                if (jg + 1 >= ig0) s[g][1] = -1.0e10f;
                if (jg     >= ig1) s[g][2] = -1.0e10f;
                if (jg + 1 >= ig1) s[g][3] = -1.0e10f;
            }
        }
        float mx0 = -3.0e38f, mx1 = -3.0e38f;
#pragma unroll
        for (int g = 0; g < 4; ++g) {
            mx0 = fmaxf(mx0, fmaxf(s[g][0], s[g][1]));
            mx1 = fmaxf(mx1, fmaxf(s[g][2], s[g][3]));
        }
        mx0 = fmaxf(mx0, __shfl_xor_sync(0xffffffffu, mx0, 1, 32));
        mx0 = fmaxf(mx0, __shfl_xor_sync(0xffffffffu, mx0, 2, 32));
        mx1 = fmaxf(mx1, __shfl_xor_sync(0xffffffffu, mx1, 1, 32));
        mx1 = fmaxf(mx1, __shfl_xor_sync(0xffffffffu, mx1, 2, 32));
        if ((l & 3) == 0) {
            rmax[(half << 6) + row0] = mx0;
            rmax[(half << 6) + row1] = mx1;
        }
        BARP(bid);

        const float rm0 = fmaxf(rmax[row0], rmax[64 + row0]);
        const float rm1 = fmaxf(rmax[row1], rmax[64 + row1]);
        const float mn0 = fmaxf(mr0, rm0), mn1 = fmaxf(mr1, rm1);
        const float a0  = exp2f((mr0 - mn0) * SCL);
        const float a1  = exp2f((mr1 - mn1) * SCL);

        // p computed in f32, packed to f16x2 (the P operand); denominator
        // sums the f16-rounded p so numerator/denominator stay consistent.
        float s0 = 0.0f, s1 = 0.0f;
#pragma unroll
        for (int g = 0; g < 4; ++g) {
            const int jg = jb0 + (g << 3) + qc;
            float p00 = (tm && jg     >= ig0) ? 0.0f : exp2f((s[g][0] - mn0) * SCL);
            float p01 = (tm && jg + 1 >= ig0) ? 0.0f : exp2f((s[g][1] - mn0) * SCL);
            float p10 = (tm && jg     >= ig1) ? 0.0f : exp2f((s[g][2] - mn1) * SCL);
            float p11 = (tm && jg + 1 >= ig1) ? 0.0f : exp2f((s[g][3] - mn1) * SCL);
            uint32_t w01 = pack_f16(p00, p01);
            uint32_t w23 = pack_f16(p10, p11);
            s0 += f16_lo(w01) + f16_hi(w01);
            s1 += f16_lo(w23) + f16_hi(w23);
            const int colb = (((half << 5) + (g << 3) + qc)) << 1;
            const int off0 = (row0 << 7) + (((colb >> 4) ^ (row0 & 7)) << 4) + (colb & 15);
            const int off1 = (row1 << 7) + (((colb >> 4) ^ (row1 & 7)) << 4) + (colb & 15);
            *(uint32_t*)(smem + SM_P + off0) = w01;
            *(uint32_t*)(smem + SM_P + off1) = w23;
        }
        s0 += __shfl_xor_sync(0xffffffffu, s0, 1, 32);
        s0 += __shfl_xor_sync(0xffffffffu, s0, 2, 32);
        s1 += __shfl_xor_sync(0xffffffffu, s1, 1, 32);
        s1 += __shfl_xor_sync(0xffffffffu, s1, 2, 32);
        if ((l & 3) == 0) {
            rsum[(half << 6) + row0] = s0;
            rsum[(half << 6) + row1] = s1;
        }
        BARP(bid);         // P + rsum ready within pair

        const float t0 = rsum[row0] + rsum[64 + row0];
        const float t1 = rsum[row1] + rsum[64 + row1];
        lr0 = lr0 * a0 + t0; lr1 = lr1 * a1 + t1;
        mr0 = mn0; mr1 = mn1;
#pragma unroll
        for (int g = 0; g < 8; ++g) {
            o[g][0] *= a0; o[g][1] *= a0; o[g][2] *= a1; o[g][3] *= a1;
        }

        // ---- O += P * V (full j, warp's c-half), single-term ----
#pragma unroll
        for (int kk = 0; kk < 4; ++kk) {
            uint32_t pa[4];
            ldsm4(frag_addr_p(sb + SM_P, p << 4, kk << 4, l), pa);
            uint32_t vf[4][4];
#pragma unroll
            for (int i = 0; i < 4; ++i) {
                const int gp = (half << 2) + i;
                ldsm4t(frag_addr(sb + SM_V, kk << 4, gp << 4, l), vf[i]);
            }
#pragma unroll
            for (int i = 0; i < 4; ++i) {
                mma16816(o[2 * i],     pa, vf[i][0], vf[i][1]);
                mma16816(o[2 * i + 1], pa, vf[i][2], vf[i][3]);
            }
        }
    }

    // ---- epilogue ----
    const float i0 = 1.0f / (lr0 + 1e-6f);
    const float i1 = 1.0f / (lr1 + 1e-6f);
    float* ob = out + bCN + m0 + (p << 4);
#pragma unroll
    for (int g = 0; g < 8; ++g) {
        const int c = (half << 6) + (g << 3) + qc;
        ob[(size_t)c * NSEQ + qr]           = o[g][0] * i0;
        ob[(size_t)(c + 1) * NSEQ + qr]     = o[g][1] * i0;
        ob[(size_t)c * NSEQ + qr + 8]       = o[g][2] * i1;
        ob[(size_t)(c + 1) * NSEQ + qr + 8] = o[g][3] * i1;
    }
}

extern "C" void kernel_launch(void* const* d_in, const int* in_sizes, int n_in,
                              void* d_out, int out_size)
{
    const float* key   = (const float*)d_in[0];
    const float* mixin = (const float*)d_in[1];
    const float* query = (const float*)d_in[2];
    float* out = (float*)d_out;

    cudaFuncSetAttribute(attn_hmma_kernel,
                         cudaFuncAttributeMaxDynamicSharedMemorySize, SMEM_BYTES);
    attn_hmma_kernel<<<512, NTHR, SMEM_BYTES>>>(key, mixin, query, out);
}

// round 12
// speedup vs baseline: 5.6559x; 1.1640x over previous
#include <cuda_runtime.h>
#include <cuda_fp16.h>
#include <cstdint>

// causal_attention: B=8, N=4096, d=128, fp32 [B,C,N] channel-major in/out.
// HMMA fp16 flash attention. R12: fully single-f16 GEMMs — S = Q*K (both
// single f16 planes), O += P*V (single-f16 P). p computed in f32 (exp2f),
// packed to f16x2; denominator sums the f16-rounded p. 2 CTAs/SM.

constexpr int NSEQ = 4096;
constexpr int CDIM = 128;
constexpr int NTHR = 256;

// per-CTA SMEM byte offsets
constexpr int SM_Q    = 0;          // 64 x 128 f16 (16KB), 256B rows, swizzled
constexpr int SM_K    = 16384;      // 64 x 128 f16 (16KB)
constexpr int SM_V    = 32768;
constexpr int SM_P    = 49152;      // 64 x 64 f16 (8KB), 128B rows
constexpr int SM_RMAX = 57344;      // 2 x 64 floats
constexpr int SM_RSUM = 57856;
constexpr int SMEM_BYTES = 58368;   // x2 CTAs = 114KB/SM

// 1/sqrt(128) * log2(e)
#define SCL 0.12751744955161f

__device__ __forceinline__ uint32_t su32(const void* p) {
    uint32_t a;
    asm("{ .reg .u64 t; cvta.to.shared.u64 t, %1; cvt.u32.u64 %0, t; }" : "=r"(a) : "l"(p));
    return a;
}
// pack two f32 -> f16x2 (lo = a, hi = b)
__device__ __forceinline__ uint32_t pack_f16(float a, float b) {
    uint32_t r;
    asm("cvt.rn.f16x2.f32 %0, %1, %2;" : "=r"(r) : "f"(b), "f"(a));
    return r;
}
__device__ __forceinline__ float f16_lo(uint32_t u) {
    float f;
    asm("{ .reg .b16 h, hh; mov.b32 {h, hh}, %1; cvt.f32.f16 %0, h; }" : "=f"(f) : "r"(u));
    return f;
}
__device__ __forceinline__ float f16_hi(uint32_t u) {
    float f;
    asm("{ .reg .b16 h, hh; mov.b32 {h, hh}, %1; cvt.f32.f16 %0, hh; }" : "=f"(f) : "r"(u));
    return f;
}

__device__ __forceinline__ void ldsm4(uint32_t addr, uint32_t* r) {
    asm volatile("ldmatrix.sync.aligned.m8n8.x4.shared.b16 {%0,%1,%2,%3}, [%4];"
                 : "=r"(r[0]), "=r"(r[1]), "=r"(r[2]), "=r"(r[3]) : "r"(addr));
}
__device__ __forceinline__ void ldsm4t(uint32_t addr, uint32_t* r) {
    asm volatile("ldmatrix.sync.aligned.m8n8.x4.trans.shared.b16 {%0,%1,%2,%3}, [%4];"
                 : "=r"(r[0]), "=r"(r[1]), "=r"(r[2]), "=r"(r[3]) : "r"(addr));
}
__device__ __forceinline__ void mma16816(float* d, const uint32_t* a,
                                         uint32_t b0, uint32_t b1) {
    asm volatile(
        "mma.sync.aligned.m16n8k16.row.col.f32.f16.f16.f32 "
        "{%0,%1,%2,%3}, {%4,%5,%6,%7}, {%8,%9}, {%0,%1,%2,%3};"
        : "+f"(d[0]), "+f"(d[1]), "+f"(d[2]), "+f"(d[3])
        : "r"(a[0]), "r"(a[1]), "r"(a[2]), "r"(a[3]), "r"(b0), "r"(b1));
}
#define BARP(id) asm volatile("bar.sync %0, 64;" :: "r"(id) : "memory")

// ldmatrix.x4 lane address: 16x16 f16 region, 256B row stride.
__device__ __forceinline__ uint32_t frag_addr(uint32_t base, int rb, int cb, int l) {
    int row = rb + (l & 7) + ((l >> 3) & 1) * 8;
    int col = cb + ((l >> 4) << 3);
    return base + (row << 8) + ((((col >> 3) ^ (row & 7)) << 4));
}
// P tile: 128B row stride.
__device__ __forceinline__ uint32_t frag_addr_p(uint32_t base, int rb, int cb, int l) {
    int row = rb + (l & 7) + ((l >> 3) & 1) * 8;
    int col = cb + ((l >> 4) << 3);
    return base + (row << 7) + ((((col >> 3) ^ (row & 7)) << 4));
}

// gmem fp32 [c][token] -> smem f16 single plane [row=token][c], 64 rows.
__device__ __forceinline__ void fill_f16(char* smem, int off,
                                         const float* gsrc, int tok0, int tid) {
#pragma unroll
    for (int q4 = 0; q4 < 4; ++q4) {
        const int it = tid + q4 * NTHR;
        const int r  = it & 63;
        const int c8 = (it >> 6) << 3;
        const float* g = gsrc + (size_t)c8 * NSEQ + tok0 + r;
        uint32_t h[4];
#pragma unroll
        for (int q = 0; q < 4; ++q)
            h[q] = pack_f16(g[(size_t)(2 * q) * NSEQ], g[(size_t)(2 * q + 1) * NSEQ]);
        const int o = (r << 8) + ((((c8 >> 3) ^ (r & 7)) << 4));
        *(uint4*)(smem + off + o) = make_uint4(h[0], h[1], h[2], h[3]);
    }
}

__global__ __launch_bounds__(NTHR, 2)
void attn_hmma_kernel(const float* __restrict__ key,
                      const float* __restrict__ mixin,
                      const float* __restrict__ query,
                      float* __restrict__ out)
{
    extern __shared__ char smem[];
    const uint32_t sb = su32(smem);

    const int tid  = threadIdx.x;
    const int l    = tid & 31;
    const int w    = tid >> 5;
    const int p    = w & 3;    // pair: q-rows 16p..16p+15 (of 64)
    const int half = w >> 2;   // 0: j 0-31 / c 0-63,  1: j 32-63 / c 64-127

    const int bx = blockIdx.x;
    const int qt = 63 - (bx >> 3);
    const int b  = bx & 7;
    const int m0 = qt << 6;

    const size_t bCN = (size_t)b * CDIM * NSEQ;
    const float* kptr = key + bCN;
    const float* vptr = mixin + bCN;

    fill_f16(smem, SM_Q, query + bCN, m0, tid);

    const int qr   = l >> 2;
    const int qc   = (l & 3) << 1;
    const int row0 = (p << 4) + qr;
    const int row1 = row0 + 8;
    const int ig0  = m0 + row0;
    const int ig1  = m0 + row1;
    const int bid  = 1 + p;

    float o[8][4];
#pragma unroll
    for (int g = 0; g < 8; ++g)
#pragma unroll
        for (int e = 0; e < 4; ++e) o[g][e] = 0.0f;
    float mr0 = -3.0e38f, mr1 = -3.0e38f, lr0 = 0.0f, lr1 = 0.0f;

    float* rmax = (float*)(smem + SM_RMAX);
    float* rsum = (float*)(smem + SM_RSUM);

    const int nkt = qt + 1;

    for (int kt = 0; kt < nkt; ++kt) {
        const int j0 = kt * 64;

        __syncthreads();   // all warps done reading K/V of kt-1 (and Q fill on kt=0)
        fill_f16(smem, SM_K, kptr, j0, tid);
        fill_f16(smem, SM_V, vptr, j0, tid);
        __syncthreads();

        // ---- S (warp's j-half) = Q * K, single f16 ----
        float s[4][4];
#pragma unroll
        for (int g = 0; g < 4; ++g)
#pragma unroll
            for (int e = 0; e < 4; ++e) s[g][e] = 0.0f;

#pragma unroll
        for (int ck = 0; ck < 8; ++ck) {
            uint32_t aq[4];
            ldsm4(frag_addr(sb + SM_Q, p << 4, ck << 4, l), aq);
            uint32_t kf[2][4];
#pragma unroll
            for (int g2 = 0; g2 < 2; ++g2) {
                const int jb = ((half << 1) + g2) << 4;
                ldsm4(frag_addr(sb + SM_K, jb, ck << 4, l), kf[g2]);
            }
#pragma unroll
            for (int g2 = 0; g2 < 2; ++g2) {
                mma16816(s[2 * g2],     aq, kf[g2][0], kf[g2][2]);
                mma16816(s[2 * g2 + 1], aq, kf[g2][1], kf[g2][3]);
            }
        }

        // ---- softmax (pair-scoped exchange) ----
        const int jb0 = j0 + (half << 5);
        const bool tm = (jb0 + 31 >= m0 + (p << 4));
        if (tm) {
#pragma unroll
            for (int g = 0; g < 4; ++g) {
                const int jg = jb0 + (g << 3) + qc;
                if (jg     >= ig0) s[g][0] = -1.0e10f;
                if (jg + 1 >= ig0) s[g][1] = -1.0e10f;
                if (jg     >= ig1) s[g][2] = -1.0e10f;
                if (jg + 1 >= ig1) s[g][3] = -1.0e10f;
            }
        }
        float mx0 = -3.0e38f, mx1 = -3.0e38f;
#pragma unroll
        for (int g = 0; g < 4; ++g) {
            mx0 = fmaxf(mx0, fmaxf(s[g][0], s[g][1]));
            mx1 = fmaxf(mx1, fmaxf(s[g][2], s[g][3]));
        }
        mx0 = fmaxf(mx0, __shfl_xor_sync(0xffffffffu, mx0, 1, 32));
        mx0 = fmaxf(mx0, __shfl_xor_sync(0xffffffffu, mx0, 2, 32));
        mx1 = fmaxf(mx1, __shfl_xor_sync(0xffffffffu, mx1, 1, 32));
        mx1 = fmaxf(mx1, __shfl_xor_sync(0xffffffffu, mx1, 2, 32));
        if ((l & 3) == 0) {
            rmax[(half << 6) + row0] = mx0;
            rmax[(half << 6) + row1] = mx1;
        }
        BARP(bid);

        const float rm0 = fmaxf(rmax[row0], rmax[64 + row0]);
        const float rm1 = fmaxf(rmax[row1], rmax[64 + row1]);
        const float mn0 = fmaxf(mr0, rm0), mn1 = fmaxf(mr1, rm1);
        const float a0  = exp2f((mr0 - mn0) * SCL);
        const float a1  = exp2f((mr1 - mn1) * SCL);

        // p in f32, packed to f16x2 (the P operand); denominator sums the
        // f16-rounded p so numerator/denominator stay consistent.
        float s0 = 0.0f, s1 = 0.0f;
#pragma unroll
        for (int g = 0; g < 4; ++g) {
            const int jg = jb0 + (g << 3) + qc;
            float p00 = (tm && jg     >= ig0) ? 0.0f : exp2f((s[g][0] - mn0) * SCL);
            float p01 = (tm && jg + 1 >= ig0) ? 0.0f : exp2f((s[g][1] - mn0) * SCL);
            float p10 = (tm && jg     >= ig1) ? 0.0f : exp2f((s[g][2] - mn1) * SCL);
            float p11 = (tm && jg + 1 >= ig1) ? 0.0f : exp2f((s[g][3] - mn1) * SCL);
            uint32_t w01 = pack_f16(p00, p01);
            uint32_t w23 = pack_f16(p10, p11);
            s0 += f16_lo(w01) + f16_hi(w01);
            s1 += f16_lo(w23) + f16_hi(w23);
            const int colb = (((half << 5) + (g << 3) + qc)) << 1;
            const int off0 = (row0 << 7) + (((colb >> 4) ^ (row0 & 7)) << 4) + (colb & 15);
            const int off1 = (row1 << 7) + (((colb >> 4) ^ (row1 & 7)) << 4) + (colb & 15);
            *(uint32_t*)(smem + SM_P + off0) = w01;
            *(uint32_t*)(smem + SM_P + off1) = w23;
        }
        s0 += __shfl_xor_sync(0xffffffffu, s0, 1, 32);
        s0 += __shfl_xor_sync(0xffffffffu, s0, 2, 32);
        s1 += __shfl_xor_sync(0xffffffffu, s1, 1, 32);
        s1 += __shfl_xor_sync(0xffffffffu, s1, 2, 32);
        if ((l & 3) == 0) {
            rsum[(half << 6) + row0] = s0;
            rsum[(half << 6) + row1] = s1;
        }
        BARP(bid);         // P + rsum ready within pair

        const float t0 = rsum[row0] + rsum[64 + row0];
        const float t1 = rsum[row1] + rsum[64 + row1];
        lr0 = lr0 * a0 + t0; lr1 = lr1 * a1 + t1;
        mr0 = mn0; mr1 = mn1;
#pragma unroll
        for (int g = 0; g < 8; ++g) {
            o[g][0] *= a0; o[g][1] *= a0; o[g][2] *= a1; o[g][3] *= a1;
        }

        // ---- O += P * V (full j, warp's c-half), single-term ----
#pragma unroll
        for (int kk = 0; kk < 4; ++kk) {
            uint32_t pa[4];
            ldsm4(frag_addr_p(sb + SM_P, p << 4, kk << 4, l), pa);
            uint32_t vf[4][4];
#pragma unroll
            for (int i = 0; i < 4; ++i) {
                const int gp = (half << 2) + i;
                ldsm4t(frag_addr(sb + SM_V, kk << 4, gp << 4, l), vf[i]);
            }
#pragma unroll
            for (int i = 0; i < 4; ++i) {
                mma16816(o[2 * i],     pa, vf[i][0], vf[i][1]);
                mma16816(o[2 * i + 1], pa, vf[i][2], vf[i][3]);
            }
        }
    }

    // ---- epilogue ----
    const float i0 = 1.0f / (lr0 + 1e-6f);
    const float i1 = 1.0f / (lr1 + 1e-6f);
    float* ob = out + bCN + m0 + (p << 4);
#pragma unroll
    for (int g = 0; g < 8; ++g) {
        const int c = (half << 6) + (g << 3) + qc;
        ob[(size_t)c * NSEQ + qr]           = o[g][0] * i0;
        ob[(size_t)(c + 1) * NSEQ + qr]     = o[g][1] * i0;
        ob[(size_t)c * NSEQ + qr + 8]       = o[g][2] * i1;
        ob[(size_t)(c + 1) * NSEQ + qr + 8] = o[g][3] * i1;
    }
}

extern "C" void kernel_launch(void* const* d_in, const int* in_sizes, int n_in,
                              void* d_out, int out_size)
{
    const float* key   = (const float*)d_in[0];
    const float* mixin = (const float*)d_in[1];
    const float* query = (const float*)d_in[2];
    float* out = (float*)d_out;

    cudaFuncSetAttribute(attn_hmma_kernel,
                         cudaFuncAttributeMaxDynamicSharedMemorySize, SMEM_BYTES);
    attn_hmma_kernel<<<512, NTHR, SMEM_BYTES>>>(key, mixin, query, out);
}